// round 9
// baseline (speedup 1.0000x reference)
#include <cuda_runtime.h>
#include <cuda_bf16.h>

// ---------------------------------------------------------------------------
// TinyGPT forward. GEMMs + attention on tensor cores (mma.sync bf16, split
// "bf16x3" accuracy). Weights pre-split per launch into bf16 hi/lo buffers.
// B=2, T=2048 (NV=256 vision + 1792 text), D=1024, H=16, DH=64, L=8,
// DFF=4096, VOCAB=32000. Output: fp32 logits [2, 1792, 32000].
// ---------------------------------------------------------------------------

#define TSEQ   2048
#define NVTOK  256
#define TTEXT  1792
#define DMODEL 1024
#define DFFDIM 4096
#define NHEAD  16
#define DHEAD  64
#define NLAYER 8
#define VOCABN 32000
#define BROWS  (2 * TSEQ)
#define MTEXT  (2 * TTEXT)

// weight-split buffer offsets (elements)
#define NW_QKV  (NLAYER * 3 * DMODEL * DMODEL)   // 25,165,824
#define NW_OUT  (NLAYER * DMODEL * DMODEL)       //  8,388,608
#define NW_FC1  (NLAYER * DFFDIM * DMODEL)       // 33,554,432
#define NW_FC2  (NLAYER * DMODEL * DFFDIM)       // 33,554,432
#define NW_HEAD (VOCABN * DMODEL)                // 32,768,000
#define OFF_OUT  NW_QKV
#define OFF_FC1  (OFF_OUT + NW_OUT)
#define OFF_FC2  (OFF_FC1 + NW_FC1)
#define OFF_HEAD (OFF_FC2 + NW_FC2)
#define NW_TOT   (OFF_HEAD + NW_HEAD)            // 133,431,296

// ------------------------- scratch (device globals) ------------------------
__device__ float g_x  [BROWS * DMODEL];
__device__ float g_h  [BROWS * DMODEL];
__device__ float g_qkv[BROWS * 3 * DMODEL];
__device__ float g_att[BROWS * DMODEL];
__device__ float g_ff [BROWS * DFFDIM];
__device__ float g_hc [MTEXT * DMODEL];
__device__ __nv_bfloat16 g_whi[NW_TOT];
__device__ __nv_bfloat16 g_wlo[NW_TOT];

// ------------------------------ helpers ------------------------------------
__device__ __forceinline__ void mma16816(float c[4], const unsigned a[4],
                                         const unsigned b[2])
{
    asm volatile(
        "mma.sync.aligned.m16n8k16.row.col.f32.bf16.bf16.f32 "
        "{%0,%1,%2,%3}, {%4,%5,%6,%7}, {%8,%9}, {%0,%1,%2,%3};"
        : "+f"(c[0]), "+f"(c[1]), "+f"(c[2]), "+f"(c[3])
        : "r"(a[0]), "r"(a[1]), "r"(a[2]), "r"(a[3]), "r"(b[0]), "r"(b[1]));
}

__device__ __forceinline__ void split2(float x, float y, unsigned& hi, unsigned& lo)
{
    __nv_bfloat16 hx = __float2bfloat16(x);
    __nv_bfloat16 hy = __float2bfloat16(y);
    __nv_bfloat162 H(hx, hy);
    hi = *(unsigned*)&H;
    __nv_bfloat162 L = __floats2bfloat162_rn(x - __bfloat162float(hx),
                                             y - __bfloat162float(hy));
    lo = *(unsigned*)&L;
}

__device__ __forceinline__ void split_store4(__nv_bfloat16* hi, __nv_bfloat16* lo,
                                             float4 v)
{
    __nv_bfloat16 h0 = __float2bfloat16(v.x);
    __nv_bfloat16 h1 = __float2bfloat16(v.y);
    __nv_bfloat16 h2 = __float2bfloat16(v.z);
    __nv_bfloat16 h3 = __float2bfloat16(v.w);
    __nv_bfloat16 l0 = __float2bfloat16(v.x - __bfloat162float(h0));
    __nv_bfloat16 l1 = __float2bfloat16(v.y - __bfloat162float(h1));
    __nv_bfloat16 l2 = __float2bfloat16(v.z - __bfloat162float(h2));
    __nv_bfloat16 l3 = __float2bfloat16(v.w - __bfloat162float(h3));
    *(__nv_bfloat162*)(hi)     = __nv_bfloat162(h0, h1);
    *(__nv_bfloat162*)(hi + 2) = __nv_bfloat162(h2, h3);
    *(__nv_bfloat162*)(lo)     = __nv_bfloat162(l0, l1);
    *(__nv_bfloat162*)(lo + 2) = __nv_bfloat162(l2, l3);
}

// ----------------------- weight pre-split (per launch) ---------------------
__global__ __launch_bounds__(256)
void split_w(const float* __restrict__ src, __nv_bfloat16* __restrict__ hi,
             __nv_bfloat16* __restrict__ lo, int n4)
{
    int i = blockIdx.x * 256 + threadIdx.x;
    if (i >= n4) return;
    float4 v = ((const float4*)src)[i];
    split_store4(hi + 4 * (size_t)i, lo + 4 * (size_t)i, v);
}

// ------------------------------- embedding ---------------------------------
__global__ __launch_bounds__(256)
void embed_kernel(const int* __restrict__ idx, const float* __restrict__ img,
                  const float* __restrict__ tok, const float* __restrict__ pos,
                  float* __restrict__ x)
{
    int i = blockIdx.x * 256 + threadIdx.x;
    int d4 = (i & 255) << 2;
    int t  = (i >> 8) & (TSEQ - 1);
    int b  = i >> 19;

    float4 base;
    if (t < NVTOK) {
        base = *(const float4*)(img + ((size_t)(b * NVTOK + t) * DMODEL) + d4);
    } else {
        int tid = idx[b * TTEXT + (t - NVTOK)];
        base = *(const float4*)(tok + (size_t)tid * DMODEL + d4);
    }
    float4 p = *(const float4*)(pos + (size_t)t * DMODEL + d4);
    base.x += p.x; base.y += p.y; base.z += p.z; base.w += p.w;
    *(float4*)(x + (size_t)(b * TSEQ + t) * DMODEL + d4) = base;
}

// ------------------------------- layernorm ---------------------------------
__global__ __launch_bounds__(256)
void ln_kernel(const float* __restrict__ x, const float* __restrict__ w,
               const float* __restrict__ bias, float* __restrict__ out, int remap)
{
    __shared__ float sh1[8];
    __shared__ float sh2[8];
    int r = blockIdx.x;
    int rin = remap ? ((r / TTEXT) * TSEQ + NVTOK + (r % TTEXT)) : r;
    int tid = threadIdx.x;

    float4 v = *(const float4*)(x + (size_t)rin * DMODEL + (tid << 2));
    float s = v.x + v.y + v.z + v.w;
    #pragma unroll
    for (int o = 16; o > 0; o >>= 1) s += __shfl_xor_sync(0xffffffffu, s, o);
    if ((tid & 31) == 0) sh1[tid >> 5] = s;
    __syncthreads();
    float tot = sh1[0] + sh1[1] + sh1[2] + sh1[3] + sh1[4] + sh1[5] + sh1[6] + sh1[7];
    float mu = tot * (1.0f / DMODEL);

    float d0 = v.x - mu, d1 = v.y - mu, d2 = v.z - mu, d3 = v.w - mu;
    float ss = d0 * d0 + d1 * d1 + d2 * d2 + d3 * d3;
    #pragma unroll
    for (int o = 16; o > 0; o >>= 1) ss += __shfl_xor_sync(0xffffffffu, ss, o);
    if ((tid & 31) == 0) sh2[tid >> 5] = ss;
    __syncthreads();
    float tot2 = sh2[0] + sh2[1] + sh2[2] + sh2[3] + sh2[4] + sh2[5] + sh2[6] + sh2[7];
    float rs = rsqrtf(tot2 * (1.0f / DMODEL) + 1e-5f);

    float4 wv = *(const float4*)(w + (tid << 2));
    float4 bv = *(const float4*)(bias + (tid << 2));
    float4 o4;
    o4.x = d0 * rs * wv.x + bv.x;
    o4.y = d1 * rs * wv.y + bv.y;
    o4.z = d2 * rs * wv.z + bv.z;
    o4.w = d3 * rs * wv.w + bv.w;
    *(float4*)(out + (size_t)r * DMODEL + (tid << 2)) = o4;
}

// ----------------------- tensor-core GEMM (bf16x3) -------------------------
// A fp32 (split on the fly); W pre-split bf16 hi/lo (pure copies into smem).
// BM=BN=128, BK=32, 256 threads, warp tile 64x32. mma issued term-major for ILP.
#define KP 40
#define BUFE (4 * 128 * KP)

template<bool BIAS, bool RELU, bool RES>
__global__ __launch_bounds__(256)
void gemm_tc(const float* __restrict__ A, const __nv_bfloat16* __restrict__ Whi,
             const __nv_bfloat16* __restrict__ Wlo,
             const float* __restrict__ bias, const float* __restrict__ Res,
             float* __restrict__ C, int M, int N, int K)
{
    extern __shared__ __nv_bfloat16 sm[];

    int n0 = blockIdx.x << 7;
    int m0 = blockIdx.y << 7;
    int tid = threadIdx.x;
    int wid = tid >> 5, lane = tid & 31;
    int grp = lane >> 2, tig = lane & 3;
    int wm = (wid >> 2) << 6;
    int wn = (wid & 3) << 5;

    // A loader: rows r0+32i, k chunk kc (fp32 -> split)
    int r0 = tid >> 3;
    int kc = (tid & 7) << 2;
    const float* Ag = A + (size_t)(m0 + r0) * K + kc;
    size_t strideA = (size_t)32 * K;

    // W loader: row wrow, half wk (bf16 copies)
    int wrow = tid >> 1;
    int wk = (tid & 1) << 4;
    const __nv_bfloat16* Whg = Whi + (size_t)(n0 + wrow) * K + wk;
    const __nv_bfloat16* Wlg = Wlo + (size_t)(n0 + wrow) * K + wk;

    float acc[4][4][4];
    #pragma unroll
    for (int mi = 0; mi < 4; mi++)
        #pragma unroll
        for (int ni = 0; ni < 4; ni++)
            #pragma unroll
            for (int q = 0; q < 4; q++) acc[mi][ni][q] = 0.f;

    float4 av[4];
    uint4 wh0, wh1, wl0, wl1;
    #pragma unroll
    for (int i = 0; i < 4; i++) av[i] = *(const float4*)(Ag + i * strideA);
    wh0 = *(const uint4*)(Whg);     wh1 = *(const uint4*)(Whg + 8);
    wl0 = *(const uint4*)(Wlg);     wl1 = *(const uint4*)(Wlg + 8);
    {
        __nv_bfloat16* Ah = sm;           __nv_bfloat16* Al = sm + 5120;
        __nv_bfloat16* Bh = sm + 10240;   __nv_bfloat16* Bl = sm + 15360;
        #pragma unroll
        for (int i = 0; i < 4; i++) {
            int off = (r0 + 32 * i) * KP + kc;
            split_store4(Ah + off, Al + off, av[i]);
        }
        int woff = wrow * KP + wk;
        *(uint4*)(Bh + woff) = wh0; *(uint4*)(Bh + woff + 8) = wh1;
        *(uint4*)(Bl + woff) = wl0; *(uint4*)(Bl + woff + 8) = wl1;
    }
    __syncthreads();

    int nk = K >> 5;
    for (int t = 0; t < nk; t++) {
        int cur = t & 1;
        bool more = (t + 1) < nk;
        if (more) {
            int kt = (t + 1) << 5;
            #pragma unroll
            for (int i = 0; i < 4; i++)
                av[i] = *(const float4*)(Ag + kt + i * strideA);
            wh0 = *(const uint4*)(Whg + kt);     wh1 = *(const uint4*)(Whg + kt + 8);
            wl0 = *(const uint4*)(Wlg + kt);     wl1 = *(const uint4*)(Wlg + kt + 8);
        }

        const __nv_bfloat16* Ah = sm + cur * BUFE;
        const __nv_bfloat16* Al = Ah + 5120;
        const __nv_bfloat16* Bh = Ah + 10240;
        const __nv_bfloat16* Bl = Ah + 15360;

        #pragma unroll
        for (int ks = 0; ks < 32; ks += 16) {
            unsigned ah[4][4], al[4][4], bh[4][2], bl[4][2];
            #pragma unroll
            for (int mi = 0; mi < 4; mi++) {
                int base = (wm + mi * 16 + grp) * KP + ks + 2 * tig;
                ah[mi][0] = *(const unsigned*)(Ah + base);
                ah[mi][1] = *(const unsigned*)(Ah + base + 8 * KP);
                ah[mi][2] = *(const unsigned*)(Ah + base + 8);
                ah[mi][3] = *(const unsigned*)(Ah + base + 8 * KP + 8);
                al[mi][0] = *(const unsigned*)(Al + base);
                al[mi][1] = *(const unsigned*)(Al + base + 8 * KP);
                al[mi][2] = *(const unsigned*)(Al + base + 8);
                al[mi][3] = *(const unsigned*)(Al + base + 8 * KP + 8);
            }
            #pragma unroll
            for (int ni = 0; ni < 4; ni++) {
                int base = (wn + ni * 8 + grp) * KP + ks + 2 * tig;
                bh[ni][0] = *(const unsigned*)(Bh + base);
                bh[ni][1] = *(const unsigned*)(Bh + base + 8);
                bl[ni][0] = *(const unsigned*)(Bl + base);
                bl[ni][1] = *(const unsigned*)(Bl + base + 8);
            }
            // term-major issue: 16 independent mma between accumulator reuses
            #pragma unroll
            for (int mi = 0; mi < 4; mi++)
                #pragma unroll
                for (int ni = 0; ni < 4; ni++)
                    mma16816(acc[mi][ni], ah[mi], bh[ni]);
            #pragma unroll
            for (int mi = 0; mi < 4; mi++)
                #pragma unroll
                for (int ni = 0; ni < 4; ni++)
                    mma16816(acc[mi][ni], ah[mi], bl[ni]);
            #pragma unroll
            for (int mi = 0; mi < 4; mi++)
                #pragma unroll
                for (int ni = 0; ni < 4; ni++)
                    mma16816(acc[mi][ni], al[mi], bh[ni]);
        }

        if (more) {
            __nv_bfloat16* Ahn = sm + (cur ^ 1) * BUFE;
            __nv_bfloat16* Aln = Ahn + 5120;
            __nv_bfloat16* Bhn = Ahn + 10240;
            __nv_bfloat16* Bln = Ahn + 15360;
            #pragma unroll
            for (int i = 0; i < 4; i++) {
                int off = (r0 + 32 * i) * KP + kc;
                split_store4(Ahn + off, Aln + off, av[i]);
            }
            int woff = wrow * KP + wk;
            *(uint4*)(Bhn + woff) = wh0; *(uint4*)(Bhn + woff + 8) = wh1;
            *(uint4*)(Bln + woff) = wl0; *(uint4*)(Bln + woff + 8) = wl1;
        }
        __syncthreads();
    }

    #pragma unroll
    for (int mi = 0; mi < 4; mi++) {
        #pragma unroll
        for (int ni = 0; ni < 4; ni++) {
            int row = m0 + wm + mi * 16 + grp;
            int col = n0 + wn + ni * 8 + 2 * tig;
            float2 v0 = make_float2(acc[mi][ni][0], acc[mi][ni][1]);
            float2 v1 = make_float2(acc[mi][ni][2], acc[mi][ni][3]);
            if (BIAS) {
                float2 bv = *(const float2*)(bias + col);
                v0.x += bv.x; v0.y += bv.y; v1.x += bv.x; v1.y += bv.y;
            }
            if (RELU) {
                v0.x = fmaxf(v0.x, 0.f); v0.y = fmaxf(v0.y, 0.f);
                v1.x = fmaxf(v1.x, 0.f); v1.y = fmaxf(v1.y, 0.f);
            }
            if (RES) {
                float2 r0v = *(const float2*)(Res + (size_t)row * N + col);
                float2 r1v = *(const float2*)(Res + (size_t)(row + 8) * N + col);
                v0.x += r0v.x; v0.y += r0v.y; v1.x += r1v.x; v1.y += r1v.y;
            }
            *(float2*)(C + (size_t)row * N + col) = v0;
            *(float2*)(C + (size_t)(row + 8) * N + col) = v1;
        }
    }
}

// ------------------- tensor-core flash attention (bf16x3) ------------------
#define AKP 72

__global__ __launch_bounds__(128)
void attn_tc(const float* __restrict__ qkv, float* __restrict__ out)
{
    const int QKVD = 3 * DMODEL;
    int qt0 = blockIdx.x << 6;
    int h = blockIdx.y, b = blockIdx.z;
    int tid = threadIdx.x;
    int warp = tid >> 5, lane = tid & 31;
    int grp = lane >> 2, tig = lane & 3;
    int wm = warp << 4;
    int hoff = h * DHEAD;

    __shared__ __nv_bfloat16 Ksh[64][AKP], Ksl[64][AKP];
    __shared__ __nv_bfloat16 Vth[64][AKP], Vtl[64][AKP];

    unsigned qh[4][4], ql[4][4];
    {
        const float* Q0 = qkv + (size_t)(b * TSEQ + qt0 + wm + grp) * QKVD + hoff;
        const float* Q1 = Q0 + (size_t)8 * QKVD;
        #pragma unroll
        for (int c = 0; c < 4; c++) {
            int k0 = 16 * c + 2 * tig;
            float2 f0 = *(const float2*)(Q0 + k0);
            float2 f1 = *(const float2*)(Q1 + k0);
            float2 f2 = *(const float2*)(Q0 + k0 + 8);
            float2 f3 = *(const float2*)(Q1 + k0 + 8);
            split2(f0.x * 0.125f, f0.y * 0.125f, qh[c][0], ql[c][0]);
            split2(f1.x * 0.125f, f1.y * 0.125f, qh[c][1], ql[c][1]);
            split2(f2.x * 0.125f, f2.y * 0.125f, qh[c][2], ql[c][2]);
            split2(f3.x * 0.125f, f3.y * 0.125f, qh[c][3], ql[c][3]);
        }
    }

    float oc[8][4];
    #pragma unroll
    for (int dt = 0; dt < 8; dt++)
        #pragma unroll
        for (int q = 0; q < 4; q++) oc[dt][q] = 0.f;
    float m0 = -1e30f, m1 = -1e30f, l0 = 0.f, l1 = 0.f;

    int qg0 = qt0 + wm + grp, qg1 = qg0 + 8;
    int ktend = (qt0 >= NVTOK) ? (qt0 + 64) : TSEQ;

    for (int kt0 = 0; kt0 < ktend; kt0 += 64) {
        #pragma unroll
        for (int i = 0; i < 8; i++) {
            int idx = tid + (i << 7);
            int key = idx >> 4, d4 = (idx & 15) << 2;
            const float* bp = qkv + (size_t)(b * TSEQ + kt0 + key) * QKVD + hoff + d4;
            float4 kv = *(const float4*)(bp + DMODEL);
            split_store4(&Ksh[key][d4], &Ksl[key][d4], kv);
            float4 vv = *(const float4*)(bp + 2 * DMODEL);
            float vf[4] = {vv.x, vv.y, vv.z, vv.w};
            #pragma unroll
            for (int j = 0; j < 4; j++) {
                __nv_bfloat16 hi = __float2bfloat16(vf[j]);
                Vth[d4 + j][key] = hi;
                Vtl[d4 + j][key] = __float2bfloat16(vf[j] - __bfloat162float(hi));
            }
        }
        __syncthreads();

        // ---- S = Q @ K^T, c-outer / nt-inner for mma ILP ----
        float sc[8][4];
        #pragma unroll
        for (int nt = 0; nt < 8; nt++)
            #pragma unroll
            for (int q = 0; q < 4; q++) sc[nt][q] = 0.f;

        #pragma unroll
        for (int c = 0; c < 4; c++) {
            unsigned bh[8][2], bl[8][2];
            int k0 = 16 * c + 2 * tig;
            #pragma unroll
            for (int nt = 0; nt < 8; nt++) {
                int krow = nt * 8 + grp;
                bh[nt][0] = *(const unsigned*)&Ksh[krow][k0];
                bh[nt][1] = *(const unsigned*)&Ksh[krow][k0 + 8];
                bl[nt][0] = *(const unsigned*)&Ksl[krow][k0];
                bl[nt][1] = *(const unsigned*)&Ksl[krow][k0 + 8];
            }
            #pragma unroll
            for (int nt = 0; nt < 8; nt++) mma16816(sc[nt], qh[c], bh[nt]);
            #pragma unroll
            for (int nt = 0; nt < 8; nt++) mma16816(sc[nt], qh[c], bl[nt]);
            #pragma unroll
            for (int nt = 0; nt < 8; nt++) mma16816(sc[nt], ql[c], bh[nt]);
        }

        // ---- mask ----
        #pragma unroll
        for (int nt = 0; nt < 8; nt++) {
            int kg0 = kt0 + nt * 8 + 2 * tig;
            int kg1 = kg0 + 1;
            if (!((qg0 < NVTOK) || (kg0 <= qg0))) sc[nt][0] = -1e30f;
            if (!((qg0 < NVTOK) || (kg1 <= qg0))) sc[nt][1] = -1e30f;
            if (!((qg1 < NVTOK) || (kg0 <= qg1))) sc[nt][2] = -1e30f;
            if (!((qg1 < NVTOK) || (kg1 <= qg1))) sc[nt][3] = -1e30f;
        }

        // ---- online softmax (lane-quad reduction) ----
        float mx0 = -1e30f, mx1 = -1e30f;
        #pragma unroll
        for (int nt = 0; nt < 8; nt++) {
            mx0 = fmaxf(mx0, fmaxf(sc[nt][0], sc[nt][1]));
            mx1 = fmaxf(mx1, fmaxf(sc[nt][2], sc[nt][3]));
        }
        mx0 = fmaxf(mx0, __shfl_xor_sync(0xffffffffu, mx0, 1));
        mx0 = fmaxf(mx0, __shfl_xor_sync(0xffffffffu, mx0, 2));
        mx1 = fmaxf(mx1, __shfl_xor_sync(0xffffffffu, mx1, 1));
        mx1 = fmaxf(mx1, __shfl_xor_sync(0xffffffffu, mx1, 2));
        float mn0 = fmaxf(m0, mx0), mn1 = fmaxf(m1, mx1);
        float al0 = __expf(m0 - mn0), al1 = __expf(m1 - mn1);
        m0 = mn0; m1 = mn1;

        float sum0 = 0.f, sum1 = 0.f;
        #pragma unroll
        for (int nt = 0; nt < 8; nt++) {
            sc[nt][0] = __expf(sc[nt][0] - mn0); sum0 += sc[nt][0];
            sc[nt][1] = __expf(sc[nt][1] - mn0); sum0 += sc[nt][1];
            sc[nt][2] = __expf(sc[nt][2] - mn1); sum1 += sc[nt][2];
            sc[nt][3] = __expf(sc[nt][3] - mn1); sum1 += sc[nt][3];
        }
        sum0 += __shfl_xor_sync(0xffffffffu, sum0, 1);
        sum0 += __shfl_xor_sync(0xffffffffu, sum0, 2);
        sum1 += __shfl_xor_sync(0xffffffffu, sum1, 1);
        sum1 += __shfl_xor_sync(0xffffffffu, sum1, 2);
        l0 = l0 * al0 + sum0;
        l1 = l1 * al1 + sum1;

        #pragma unroll
        for (int dt = 0; dt < 8; dt++) {
            oc[dt][0] *= al0; oc[dt][1] *= al0;
            oc[dt][2] *= al1; oc[dt][3] *= al1;
        }

        // ---- re-pack P (C-frag -> A-frag), hi/lo ----
        unsigned ph[4][4], pl[4][4];
        #pragma unroll
        for (int c = 0; c < 4; c++) {
            split2(sc[2 * c][0],     sc[2 * c][1],     ph[c][0], pl[c][0]);
            split2(sc[2 * c][2],     sc[2 * c][3],     ph[c][1], pl[c][1]);
            split2(sc[2 * c + 1][0], sc[2 * c + 1][1], ph[c][2], pl[c][2]);
            split2(sc[2 * c + 1][2], sc[2 * c + 1][3], ph[c][3], pl[c][3]);
        }

        // ---- O += P @ V, c-outer / dt-inner for mma ILP ----
        #pragma unroll
        for (int c = 0; c < 4; c++) {
            unsigned bh[8][2], bl[8][2];
            int k0 = 16 * c + 2 * tig;
            #pragma unroll
            for (int dt = 0; dt < 8; dt++) {
                int drow = dt * 8 + grp;
                bh[dt][0] = *(const unsigned*)&Vth[drow][k0];
                bh[dt][1] = *(const unsigned*)&Vth[drow][k0 + 8];
                bl[dt][0] = *(const unsigned*)&Vtl[drow][k0];
                bl[dt][1] = *(const unsigned*)&Vtl[drow][k0 + 8];
            }
            #pragma unroll
            for (int dt = 0; dt < 8; dt++) mma16816(oc[dt], ph[c], bh[dt]);
            #pragma unroll
            for (int dt = 0; dt < 8; dt++) mma16816(oc[dt], ph[c], bl[dt]);
            #pragma unroll
            for (int dt = 0; dt < 8; dt++) mma16816(oc[dt], pl[c], bh[dt]);
        }
        __syncthreads();
    }

    float inv0 = 1.f / l0, inv1 = 1.f / l1;
    float* o0 = out + (size_t)(b * TSEQ + qg0) * DMODEL + hoff;
    float* o1 = out + (size_t)(b * TSEQ + qg1) * DMODEL + hoff;
    #pragma unroll
    for (int dt = 0; dt < 8; dt++) {
        int dcol = dt * 8 + 2 * tig;
        *(float2*)(o0 + dcol) = make_float2(oc[dt][0] * inv0, oc[dt][1] * inv0);
        *(float2*)(o1 + dcol) = make_float2(oc[dt][2] * inv1, oc[dt][3] * inv1);
    }
}

// -------------------------------- launcher ---------------------------------
#define GEMM_SMEM 81920

extern "C" void kernel_launch(void* const* d_in, const int* in_sizes, int n_in,
                              void* d_out, int out_size)
{
    (void)in_sizes; (void)n_in; (void)out_size;
    const int*   idx   = (const int*)  d_in[0];
    const float* img   = (const float*)d_in[1];
    const float* tok   = (const float*)d_in[2];
    const float* pos   = (const float*)d_in[3];
    const float* ln1w  = (const float*)d_in[4];
    const float* ln1b  = (const float*)d_in[5];
    const float* qkvw  = (const float*)d_in[6];
    const float* outw  = (const float*)d_in[7];
    const float* ln2w  = (const float*)d_in[8];
    const float* ln2b  = (const float*)d_in[9];
    const float* fc1w  = (const float*)d_in[10];
    const float* fc1b  = (const float*)d_in[11];
    const float* fc2w  = (const float*)d_in[12];
    const float* fc2b  = (const float*)d_in[13];
    const float* lnfw  = (const float*)d_in[14];
    const float* lnfb  = (const float*)d_in[15];
    const float* headw = (const float*)d_in[16];
    float* out = (float*)d_out;

    float *x, *h, *qkv, *att, *ff, *hc;
    __nv_bfloat16 *whi, *wlo;
    cudaGetSymbolAddress((void**)&x,   g_x);
    cudaGetSymbolAddress((void**)&h,   g_h);
    cudaGetSymbolAddress((void**)&qkv, g_qkv);
    cudaGetSymbolAddress((void**)&att, g_att);
    cudaGetSymbolAddress((void**)&ff,  g_ff);
    cudaGetSymbolAddress((void**)&hc,  g_hc);
    cudaGetSymbolAddress((void**)&whi, g_whi);
    cudaGetSymbolAddress((void**)&wlo, g_wlo);

    static int attr_done = 0;
    if (!attr_done) {
        cudaFuncSetAttribute(gemm_tc<false, false, false>,
                             cudaFuncAttributeMaxDynamicSharedMemorySize, GEMM_SMEM);
        cudaFuncSetAttribute(gemm_tc<false, false, true>,
                             cudaFuncAttributeMaxDynamicSharedMemorySize, GEMM_SMEM);
        cudaFuncSetAttribute(gemm_tc<true, true, false>,
                             cudaFuncAttributeMaxDynamicSharedMemorySize, GEMM_SMEM);
        cudaFuncSetAttribute(gemm_tc<true, false, true>,
                             cudaFuncAttributeMaxDynamicSharedMemorySize, GEMM_SMEM);
        attr_done = 1;
    }

    // weight pre-split (per launch; graph-capturable, deterministic)
    split_w<<<(NW_QKV / 4 + 255) / 256, 256>>>(qkvw,  whi,            wlo,            NW_QKV / 4);
    split_w<<<(NW_OUT / 4 + 255) / 256, 256>>>(outw,  whi + OFF_OUT,  wlo + OFF_OUT,  NW_OUT / 4);
    split_w<<<(NW_FC1 / 4 + 255) / 256, 256>>>(fc1w,  whi + OFF_FC1,  wlo + OFF_FC1,  NW_FC1 / 4);
    split_w<<<(NW_FC2 / 4 + 255) / 256, 256>>>(fc2w,  whi + OFF_FC2,  wlo + OFF_FC2,  NW_FC2 / 4);
    split_w<<<(NW_HEAD / 4 + 255) / 256, 256>>>(headw, whi + OFF_HEAD, wlo + OFF_HEAD, NW_HEAD / 4);

    embed_kernel<<<4096, 256>>>(idx, img, tok, pos, x);

    for (int l = 0; l < NLAYER; l++) {
        size_t oq = (size_t)l * 3 * DMODEL * DMODEL;
        size_t oo = OFF_OUT + (size_t)l * DMODEL * DMODEL;
        size_t o1 = OFF_FC1 + (size_t)l * DFFDIM * DMODEL;
        size_t o2 = OFF_FC2 + (size_t)l * DMODEL * DFFDIM;

        ln_kernel<<<BROWS, 256>>>(x, ln1w + l * DMODEL, ln1b + l * DMODEL, h, 0);
        gemm_tc<false, false, false><<<dim3(3 * DMODEL / 128, BROWS / 128), 256, GEMM_SMEM>>>(
            h, whi + oq, wlo + oq, nullptr, nullptr, qkv, BROWS, 3 * DMODEL, DMODEL);
        attn_tc<<<dim3(TSEQ / 64, NHEAD, 2), 128>>>(qkv, att);
        gemm_tc<false, false, true><<<dim3(DMODEL / 128, BROWS / 128), 256, GEMM_SMEM>>>(
            att, whi + oo, wlo + oo, nullptr, x, x, BROWS, DMODEL, DMODEL);
        ln_kernel<<<BROWS, 256>>>(x, ln2w + l * DMODEL, ln2b + l * DMODEL, h, 0);
        gemm_tc<true, true, false><<<dim3(DFFDIM / 128, BROWS / 128), 256, GEMM_SMEM>>>(
            h, whi + o1, wlo + o1, fc1b + l * DFFDIM, nullptr, ff, BROWS, DFFDIM, DMODEL);
        gemm_tc<true, false, true><<<dim3(DMODEL / 128, BROWS / 128), 256, GEMM_SMEM>>>(
            ff, whi + o2, wlo + o2, fc2b + l * DMODEL, x, x, BROWS, DMODEL, DFFDIM);
    }

    ln_kernel<<<MTEXT, 256>>>(x, lnfw, lnfb, hc, 1);
    gemm_tc<false, false, false><<<dim3(VOCABN / 128, MTEXT / 128), 256, GEMM_SMEM>>>(
        hc, whi + OFF_HEAD, wlo + OFF_HEAD, nullptr, nullptr, out, MTEXT, VOCABN, DMODEL);
}

// round 10
// speedup vs baseline: 1.1845x; 1.1845x over previous
#include <cuda_runtime.h>
#include <cuda_bf16.h>

// ---------------------------------------------------------------------------
// TinyGPT forward. GEMMs + attention on tensor cores (mma.sync bf16, split
// "bf16x3" accuracy), fragment loads via ldmatrix. LN/embed fp32 SIMT.
// B=2, T=2048 (NV=256 vision + 1792 text), D=1024, H=16, DH=64, L=8,
// DFF=4096, VOCAB=32000. Output: fp32 logits [2, 1792, 32000].
// ---------------------------------------------------------------------------

#define TSEQ   2048
#define NVTOK  256
#define TTEXT  1792
#define DMODEL 1024
#define DFFDIM 4096
#define NHEAD  16
#define DHEAD  64
#define NLAYER 8
#define VOCABN 32000
#define BROWS  (2 * TSEQ)
#define MTEXT  (2 * TTEXT)

// ------------------------- scratch (device globals) ------------------------
__device__ float g_x  [BROWS * DMODEL];
__device__ float g_h  [BROWS * DMODEL];
__device__ float g_qkv[BROWS * 3 * DMODEL];
__device__ float g_att[BROWS * DMODEL];
__device__ float g_ff [BROWS * DFFDIM];
__device__ float g_hc [MTEXT * DMODEL];

// ------------------------------ helpers ------------------------------------
__device__ __forceinline__ void mma16816(float c[4], const unsigned a[4],
                                         const unsigned b[2])
{
    asm volatile(
        "mma.sync.aligned.m16n8k16.row.col.f32.bf16.bf16.f32 "
        "{%0,%1,%2,%3}, {%4,%5,%6,%7}, {%8,%9}, {%0,%1,%2,%3};"
        : "+f"(c[0]), "+f"(c[1]), "+f"(c[2]), "+f"(c[3])
        : "r"(a[0]), "r"(a[1]), "r"(a[2]), "r"(a[3]), "r"(b[0]), "r"(b[1]));
}

__device__ __forceinline__ void ldm_x4(unsigned r[4], unsigned addr)
{
    asm volatile(
        "ldmatrix.sync.aligned.m8n8.x4.shared.b16 {%0,%1,%2,%3}, [%4];"
        : "=r"(r[0]), "=r"(r[1]), "=r"(r[2]), "=r"(r[3]) : "r"(addr));
}

__device__ __forceinline__ void split2(float x, float y, unsigned& hi, unsigned& lo)
{
    __nv_bfloat16 hx = __float2bfloat16(x);
    __nv_bfloat16 hy = __float2bfloat16(y);
    __nv_bfloat162 H(hx, hy);
    hi = *(unsigned*)&H;
    __nv_bfloat162 L = __floats2bfloat162_rn(x - __bfloat162float(hx),
                                             y - __bfloat162float(hy));
    lo = *(unsigned*)&L;
}

__device__ __forceinline__ void split_store4(__nv_bfloat16* hi, __nv_bfloat16* lo,
                                             float4 v)
{
    __nv_bfloat16 h0 = __float2bfloat16(v.x);
    __nv_bfloat16 h1 = __float2bfloat16(v.y);
    __nv_bfloat16 h2 = __float2bfloat16(v.z);
    __nv_bfloat16 h3 = __float2bfloat16(v.w);
    __nv_bfloat16 l0 = __float2bfloat16(v.x - __bfloat162float(h0));
    __nv_bfloat16 l1 = __float2bfloat16(v.y - __bfloat162float(h1));
    __nv_bfloat16 l2 = __float2bfloat16(v.z - __bfloat162float(h2));
    __nv_bfloat16 l3 = __float2bfloat16(v.w - __bfloat162float(h3));
    *(__nv_bfloat162*)(hi)     = __nv_bfloat162(h0, h1);
    *(__nv_bfloat162*)(hi + 2) = __nv_bfloat162(h2, h3);
    *(__nv_bfloat162*)(lo)     = __nv_bfloat162(l0, l1);
    *(__nv_bfloat162*)(lo + 2) = __nv_bfloat162(l2, l3);
}

// ------------------------------- embedding ---------------------------------
__global__ __launch_bounds__(256)
void embed_kernel(const int* __restrict__ idx, const float* __restrict__ img,
                  const float* __restrict__ tok, const float* __restrict__ pos,
                  float* __restrict__ x)
{
    int i = blockIdx.x * 256 + threadIdx.x;
    int d4 = (i & 255) << 2;
    int t  = (i >> 8) & (TSEQ - 1);
    int b  = i >> 19;

    float4 base;
    if (t < NVTOK) {
        base = *(const float4*)(img + ((size_t)(b * NVTOK + t) * DMODEL) + d4);
    } else {
        int tid = idx[b * TTEXT + (t - NVTOK)];
        base = *(const float4*)(tok + (size_t)tid * DMODEL + d4);
    }
    float4 p = *(const float4*)(pos + (size_t)t * DMODEL + d4);
    base.x += p.x; base.y += p.y; base.z += p.z; base.w += p.w;
    *(float4*)(x + (size_t)(b * TSEQ + t) * DMODEL + d4) = base;
}

// ------------------------------- layernorm ---------------------------------
__global__ __launch_bounds__(256)
void ln_kernel(const float* __restrict__ x, const float* __restrict__ w,
               const float* __restrict__ bias, float* __restrict__ out, int remap)
{
    __shared__ float sh1[8];
    __shared__ float sh2[8];
    int r = blockIdx.x;
    int rin = remap ? ((r / TTEXT) * TSEQ + NVTOK + (r % TTEXT)) : r;
    int tid = threadIdx.x;

    float4 v = *(const float4*)(x + (size_t)rin * DMODEL + (tid << 2));
    float s = v.x + v.y + v.z + v.w;
    #pragma unroll
    for (int o = 16; o > 0; o >>= 1) s += __shfl_xor_sync(0xffffffffu, s, o);
    if ((tid & 31) == 0) sh1[tid >> 5] = s;
    __syncthreads();
    float tot = sh1[0] + sh1[1] + sh1[2] + sh1[3] + sh1[4] + sh1[5] + sh1[6] + sh1[7];
    float mu = tot * (1.0f / DMODEL);

    float d0 = v.x - mu, d1 = v.y - mu, d2 = v.z - mu, d3 = v.w - mu;
    float ss = d0 * d0 + d1 * d1 + d2 * d2 + d3 * d3;
    #pragma unroll
    for (int o = 16; o > 0; o >>= 1) ss += __shfl_xor_sync(0xffffffffu, ss, o);
    if ((tid & 31) == 0) sh2[tid >> 5] = ss;
    __syncthreads();
    float tot2 = sh2[0] + sh2[1] + sh2[2] + sh2[3] + sh2[4] + sh2[5] + sh2[6] + sh2[7];
    float rs = rsqrtf(tot2 * (1.0f / DMODEL) + 1e-5f);

    float4 wv = *(const float4*)(w + (tid << 2));
    float4 bv = *(const float4*)(bias + (tid << 2));
    float4 o4;
    o4.x = d0 * rs * wv.x + bv.x;
    o4.y = d1 * rs * wv.y + bv.y;
    o4.z = d2 * rs * wv.z + bv.z;
    o4.w = d3 * rs * wv.w + bv.w;
    *(float4*)(out + (size_t)r * DMODEL + (tid << 2)) = o4;
}

// ----------------------- tensor-core GEMM (bf16x3) -------------------------
// Round-8 structure (on-the-fly hi/lo split of A and W); fragment loads via
// ldmatrix.x4. BM=BN=128, BK=32, 256 threads, warp tile 64x32.
#define KP 40
#define BUFE (4 * 128 * KP)

template<bool BIAS, bool RELU, bool RES>
__global__ __launch_bounds__(256)
void gemm_tc(const float* __restrict__ A, const float* __restrict__ W,
             const float* __restrict__ bias, const float* __restrict__ Res,
             float* __restrict__ C, int M, int N, int K)
{
    extern __shared__ __nv_bfloat16 sm[];

    int n0 = blockIdx.x << 7;
    int m0 = blockIdx.y << 7;
    int tid = threadIdx.x;
    int wid = tid >> 5, lane = tid & 31;
    int grp = lane >> 2, tig = lane & 3;
    int lt = lane & 7, seg = lane >> 3;
    int wm = (wid >> 2) << 6;
    int wn = (wid & 3) << 5;

    int r0 = tid >> 3;
    int kc = (tid & 7) << 2;
    const float* Ag = A + (size_t)(m0 + r0) * K + kc;
    const float* Wg = W + (size_t)(n0 + r0) * K + kc;
    size_t strideA = (size_t)32 * K;

    // ldmatrix per-lane element offsets (add ks before use)
    unsigned smbase = (unsigned)__cvta_generic_to_shared(sm);
    int aoff[4], boff[2];
    #pragma unroll
    for (int mi = 0; mi < 4; mi++)
        aoff[mi] = (wm + mi * 16 + (seg & 1) * 8 + lt) * KP + (seg >> 1) * 8;
    #pragma unroll
    for (int p = 0; p < 2; p++)
        boff[p] = (wn + (2 * p + (seg >> 1)) * 8 + lt) * KP + (seg & 1) * 8;

    float acc[4][4][4];
    #pragma unroll
    for (int mi = 0; mi < 4; mi++)
        #pragma unroll
        for (int ni = 0; ni < 4; ni++)
            #pragma unroll
            for (int q = 0; q < 4; q++) acc[mi][ni][q] = 0.f;

    float4 av[4], wv[4];
    #pragma unroll
    for (int i = 0; i < 4; i++) {
        av[i] = *(const float4*)(Ag + i * strideA);
        wv[i] = *(const float4*)(Wg + i * strideA);
    }
    {
        __nv_bfloat16* Ah = sm;           __nv_bfloat16* Al = sm + 5120;
        __nv_bfloat16* Bh = sm + 10240;   __nv_bfloat16* Bl = sm + 15360;
        #pragma unroll
        for (int i = 0; i < 4; i++) {
            int off = (r0 + 32 * i) * KP + kc;
            split_store4(Ah + off, Al + off, av[i]);
            split_store4(Bh + off, Bl + off, wv[i]);
        }
    }
    __syncthreads();

    int nk = K >> 5;
    for (int t = 0; t < nk; t++) {
        int cur = t & 1;
        bool more = (t + 1) < nk;
        if (more) {
            int kt = (t + 1) << 5;
            #pragma unroll
            for (int i = 0; i < 4; i++) {
                av[i] = *(const float4*)(Ag + kt + i * strideA);
                wv[i] = *(const float4*)(Wg + kt + i * strideA);
            }
        }

        unsigned Ah_b = smbase + cur * (BUFE * 2);
        unsigned Al_b = Ah_b + 5120 * 2;
        unsigned Bh_b = Ah_b + 10240 * 2;
        unsigned Bl_b = Ah_b + 15360 * 2;

        #pragma unroll
        for (int ks = 0; ks < 32; ks += 16) {
            unsigned ah[4][4], al[4][4], bhb[2][4], blb[2][4];
            #pragma unroll
            for (int mi = 0; mi < 4; mi++)
                ldm_x4(ah[mi], Ah_b + (unsigned)(aoff[mi] + ks) * 2);
            #pragma unroll
            for (int mi = 0; mi < 4; mi++)
                ldm_x4(al[mi], Al_b + (unsigned)(aoff[mi] + ks) * 2);
            #pragma unroll
            for (int p = 0; p < 2; p++)
                ldm_x4(bhb[p], Bh_b + (unsigned)(boff[p] + ks) * 2);
            #pragma unroll
            for (int p = 0; p < 2; p++)
                ldm_x4(blb[p], Bl_b + (unsigned)(boff[p] + ks) * 2);

            #pragma unroll
            for (int mi = 0; mi < 4; mi++)
                #pragma unroll
                for (int ni = 0; ni < 4; ni++) {
                    const unsigned* bh = &bhb[ni >> 1][(ni & 1) * 2];
                    const unsigned* bl = &blb[ni >> 1][(ni & 1) * 2];
                    mma16816(acc[mi][ni], ah[mi], bh);
                    mma16816(acc[mi][ni], ah[mi], bl);
                    mma16816(acc[mi][ni], al[mi], bh);
                }
        }

        if (more) {
            __nv_bfloat16* Ahn = sm + (cur ^ 1) * BUFE;
            __nv_bfloat16* Aln = Ahn + 5120;
            __nv_bfloat16* Bhn = Ahn + 10240;
            __nv_bfloat16* Bln = Ahn + 15360;
            #pragma unroll
            for (int i = 0; i < 4; i++) {
                int off = (r0 + 32 * i) * KP + kc;
                split_store4(Ahn + off, Aln + off, av[i]);
                split_store4(Bhn + off, Bln + off, wv[i]);
            }
        }
        __syncthreads();
    }

    #pragma unroll
    for (int mi = 0; mi < 4; mi++) {
        #pragma unroll
        for (int ni = 0; ni < 4; ni++) {
            int row = m0 + wm + mi * 16 + grp;
            int col = n0 + wn + ni * 8 + 2 * tig;
            float2 v0 = make_float2(acc[mi][ni][0], acc[mi][ni][1]);
            float2 v1 = make_float2(acc[mi][ni][2], acc[mi][ni][3]);
            if (BIAS) {
                float2 bv = *(const float2*)(bias + col);
                v0.x += bv.x; v0.y += bv.y; v1.x += bv.x; v1.y += bv.y;
            }
            if (RELU) {
                v0.x = fmaxf(v0.x, 0.f); v0.y = fmaxf(v0.y, 0.f);
                v1.x = fmaxf(v1.x, 0.f); v1.y = fmaxf(v1.y, 0.f);
            }
            if (RES) {
                float2 r0v = *(const float2*)(Res + (size_t)row * N + col);
                float2 r1v = *(const float2*)(Res + (size_t)(row + 8) * N + col);
                v0.x += r0v.x; v0.y += r0v.y; v1.x += r1v.x; v1.y += r1v.y;
            }
            *(float2*)(C + (size_t)row * N + col) = v0;
            *(float2*)(C + (size_t)(row + 8) * N + col) = v1;
        }
    }
}

// ------------------- tensor-core flash attention (bf16x3) ------------------
#define AKP 72

__global__ __launch_bounds__(128)
void attn_tc(const float* __restrict__ qkv, float* __restrict__ out)
{
    const int QKVD = 3 * DMODEL;
    int qt0 = blockIdx.x << 6;
    int h = blockIdx.y, b = blockIdx.z;
    int tid = threadIdx.x;
    int warp = tid >> 5, lane = tid & 31;
    int grp = lane >> 2, tig = lane & 3;
    int lt = lane & 7, seg = lane >> 3;
    int wm = warp << 4;
    int hoff = h * DHEAD;

    __shared__ __nv_bfloat16 Ksh[64][AKP], Ksl[64][AKP];
    __shared__ __nv_bfloat16 Vth[64][AKP], Vtl[64][AKP];

    unsigned Kh_b = (unsigned)__cvta_generic_to_shared(&Ksh[0][0]);
    unsigned Kl_b = (unsigned)__cvta_generic_to_shared(&Ksl[0][0]);
    unsigned Vh_b = (unsigned)__cvta_generic_to_shared(&Vth[0][0]);
    unsigned Vl_b = (unsigned)__cvta_generic_to_shared(&Vtl[0][0]);

    // ldmatrix lane offsets: pair p covers atoms 2p, 2p+1 (rows), k split by seg
    int poff[4];
    #pragma unroll
    for (int p = 0; p < 4; p++)
        poff[p] = ((2 * p + (seg >> 1)) * 8 + lt) * AKP + (seg & 1) * 8;

    unsigned qh[4][4], ql[4][4];
    {
        const float* Q0 = qkv + (size_t)(b * TSEQ + qt0 + wm + grp) * QKVD + hoff;
        const float* Q1 = Q0 + (size_t)8 * QKVD;
        #pragma unroll
        for (int c = 0; c < 4; c++) {
            int k0 = 16 * c + 2 * tig;
            float2 f0 = *(const float2*)(Q0 + k0);
            float2 f1 = *(const float2*)(Q1 + k0);
            float2 f2 = *(const float2*)(Q0 + k0 + 8);
            float2 f3 = *(const float2*)(Q1 + k0 + 8);
            split2(f0.x * 0.125f, f0.y * 0.125f, qh[c][0], ql[c][0]);
            split2(f1.x * 0.125f, f1.y * 0.125f, qh[c][1], ql[c][1]);
            split2(f2.x * 0.125f, f2.y * 0.125f, qh[c][2], ql[c][2]);
            split2(f3.x * 0.125f, f3.y * 0.125f, qh[c][3], ql[c][3]);
        }
    }

    float oc[8][4];
    #pragma unroll
    for (int dt = 0; dt < 8; dt++)
        #pragma unroll
        for (int q = 0; q < 4; q++) oc[dt][q] = 0.f;
    float m0 = -1e30f, m1 = -1e30f, l0 = 0.f, l1 = 0.f;

    int qg0 = qt0 + wm + grp, qg1 = qg0 + 8;
    int ktend = (qt0 >= NVTOK) ? (qt0 + 64) : TSEQ;

    for (int kt0 = 0; kt0 < ktend; kt0 += 64) {
        #pragma unroll
        for (int i = 0; i < 8; i++) {
            int idx = tid + (i << 7);
            int key = idx >> 4, d4 = (idx & 15) << 2;
            const float* bp = qkv + (size_t)(b * TSEQ + kt0 + key) * QKVD + hoff + d4;
            float4 kv = *(const float4*)(bp + DMODEL);
            split_store4(&Ksh[key][d4], &Ksl[key][d4], kv);
            float4 vv = *(const float4*)(bp + 2 * DMODEL);
            float vf[4] = {vv.x, vv.y, vv.z, vv.w};
            #pragma unroll
            for (int j = 0; j < 4; j++) {
                __nv_bfloat16 hi = __float2bfloat16(vf[j]);
                Vth[d4 + j][key] = hi;
                Vtl[d4 + j][key] = __float2bfloat16(vf[j] - __bfloat162float(hi));
            }
        }
        __syncthreads();

        // ---- S = Q @ K^T ----
        float sc[8][4];
        #pragma unroll
        for (int nt = 0; nt < 8; nt++)
            #pragma unroll
            for (int q = 0; q < 4; q++) sc[nt][q] = 0.f;

        #pragma unroll
        for (int c = 0; c < 4; c++) {
            unsigned bhb[4][4], blb[4][4];
            #pragma unroll
            for (int p = 0; p < 4; p++)
                ldm_x4(bhb[p], Kh_b + (unsigned)(poff[p] + 16 * c) * 2);
            #pragma unroll
            for (int p = 0; p < 4; p++)
                ldm_x4(blb[p], Kl_b + (unsigned)(poff[p] + 16 * c) * 2);
            #pragma unroll
            for (int nt = 0; nt < 8; nt++) {
                const unsigned* bh = &bhb[nt >> 1][(nt & 1) * 2];
                const unsigned* bl = &blb[nt >> 1][(nt & 1) * 2];
                mma16816(sc[nt], qh[c], bh);
                mma16816(sc[nt], qh[c], bl);
                mma16816(sc[nt], ql[c], bh);
            }
        }

        // ---- mask ----
        #pragma unroll
        for (int nt = 0; nt < 8; nt++) {
            int kg0 = kt0 + nt * 8 + 2 * tig;
            int kg1 = kg0 + 1;
            if (!((qg0 < NVTOK) || (kg0 <= qg0))) sc[nt][0] = -1e30f;
            if (!((qg0 < NVTOK) || (kg1 <= qg0))) sc[nt][1] = -1e30f;
            if (!((qg1 < NVTOK) || (kg0 <= qg1))) sc[nt][2] = -1e30f;
            if (!((qg1 < NVTOK) || (kg1 <= qg1))) sc[nt][3] = -1e30f;
        }

        // ---- online softmax (lane-quad reduction) ----
        float mx0 = -1e30f, mx1 = -1e30f;
        #pragma unroll
        for (int nt = 0; nt < 8; nt++) {
            mx0 = fmaxf(mx0, fmaxf(sc[nt][0], sc[nt][1]));
            mx1 = fmaxf(mx1, fmaxf(sc[nt][2], sc[nt][3]));
        }
        mx0 = fmaxf(mx0, __shfl_xor_sync(0xffffffffu, mx0, 1));
        mx0 = fmaxf(mx0, __shfl_xor_sync(0xffffffffu, mx0, 2));
        mx1 = fmaxf(mx1, __shfl_xor_sync(0xffffffffu, mx1, 1));
        mx1 = fmaxf(mx1, __shfl_xor_sync(0xffffffffu, mx1, 2));
        float mn0 = fmaxf(m0, mx0), mn1 = fmaxf(m1, mx1);
        float al0 = __expf(m0 - mn0), al1 = __expf(m1 - mn1);
        m0 = mn0; m1 = mn1;

        float sum0 = 0.f, sum1 = 0.f;
        #pragma unroll
        for (int nt = 0; nt < 8; nt++) {
            sc[nt][0] = __expf(sc[nt][0] - mn0); sum0 += sc[nt][0];
            sc[nt][1] = __expf(sc[nt][1] - mn0); sum0 += sc[nt][1];
            sc[nt][2] = __expf(sc[nt][2] - mn1); sum1 += sc[nt][2];
            sc[nt][3] = __expf(sc[nt][3] - mn1); sum1 += sc[nt][3];
        }
        sum0 += __shfl_xor_sync(0xffffffffu, sum0, 1);
        sum0 += __shfl_xor_sync(0xffffffffu, sum0, 2);
        sum1 += __shfl_xor_sync(0xffffffffu, sum1, 1);
        sum1 += __shfl_xor_sync(0xffffffffu, sum1, 2);
        l0 = l0 * al0 + sum0;
        l1 = l1 * al1 + sum1;

        #pragma unroll
        for (int dt = 0; dt < 8; dt++) {
            oc[dt][0] *= al0; oc[dt][1] *= al0;
            oc[dt][2] *= al1; oc[dt][3] *= al1;
        }

        // ---- re-pack P (C-frag -> A-frag), hi/lo ----
        unsigned ph[4][4], pl[4][4];
        #pragma unroll
        for (int c = 0; c < 4; c++) {
            split2(sc[2 * c][0],     sc[2 * c][1],     ph[c][0], pl[c][0]);
            split2(sc[2 * c][2],     sc[2 * c][3],     ph[c][1], pl[c][1]);
            split2(sc[2 * c + 1][0], sc[2 * c + 1][1], ph[c][2], pl[c][2]);
            split2(sc[2 * c + 1][2], sc[2 * c + 1][3], ph[c][3], pl[c][3]);
        }

        // ---- O += P @ V ----
        #pragma unroll
        for (int c = 0; c < 4; c++) {
            unsigned bhb[4][4], blb[4][4];
            #pragma unroll
            for (int p = 0; p < 4; p++)
                ldm_x4(bhb[p], Vh_b + (unsigned)(poff[p] + 16 * c) * 2);
            #pragma unroll
            for (int p = 0; p < 4; p++)
                ldm_x4(blb[p], Vl_b + (unsigned)(poff[p] + 16 * c) * 2);
            #pragma unroll
            for (int dt = 0; dt < 8; dt++) {
                const unsigned* bh = &bhb[dt >> 1][(dt & 1) * 2];
                const unsigned* bl = &blb[dt >> 1][(dt & 1) * 2];
                mma16816(oc[dt], ph[c], bh);
                mma16816(oc[dt], ph[c], bl);
                mma16816(oc[dt], pl[c], bh);
            }
        }
        __syncthreads();
    }

    float inv0 = 1.f / l0, inv1 = 1.f / l1;
    float* o0 = out + (size_t)(b * TSEQ + qg0) * DMODEL + hoff;
    float* o1 = out + (size_t)(b * TSEQ + qg1) * DMODEL + hoff;
    #pragma unroll
    for (int dt = 0; dt < 8; dt++) {
        int dcol = dt * 8 + 2 * tig;
        *(float2*)(o0 + dcol) = make_float2(oc[dt][0] * inv0, oc[dt][1] * inv0);
        *(float2*)(o1 + dcol) = make_float2(oc[dt][2] * inv1, oc[dt][3] * inv1);
    }
}

// -------------------------------- launcher ---------------------------------
#define GEMM_SMEM 81920

extern "C" void kernel_launch(void* const* d_in, const int* in_sizes, int n_in,
                              void* d_out, int out_size)
{
    (void)in_sizes; (void)n_in; (void)out_size;
    const int*   idx   = (const int*)  d_in[0];
    const float* img   = (const float*)d_in[1];
    const float* tok   = (const float*)d_in[2];
    const float* pos   = (const float*)d_in[3];
    const float* ln1w  = (const float*)d_in[4];
    const float* ln1b  = (const float*)d_in[5];
    const float* qkvw  = (const float*)d_in[6];
    const float* outw  = (const float*)d_in[7];
    const float* ln2w  = (const float*)d_in[8];
    const float* ln2b  = (const float*)d_in[9];
    const float* fc1w  = (const float*)d_in[10];
    const float* fc1b  = (const float*)d_in[11];
    const float* fc2w  = (const float*)d_in[12];
    const float* fc2b  = (const float*)d_in[13];
    const float* lnfw  = (const float*)d_in[14];
    const float* lnfb  = (const float*)d_in[15];
    const float* headw = (const float*)d_in[16];
    float* out = (float*)d_out;

    float *x, *h, *qkv, *att, *ff, *hc;
    cudaGetSymbolAddress((void**)&x,   g_x);
    cudaGetSymbolAddress((void**)&h,   g_h);
    cudaGetSymbolAddress((void**)&qkv, g_qkv);
    cudaGetSymbolAddress((void**)&att, g_att);
    cudaGetSymbolAddress((void**)&ff,  g_ff);
    cudaGetSymbolAddress((void**)&hc,  g_hc);

    static int attr_done = 0;
    if (!attr_done) {
        cudaFuncSetAttribute(gemm_tc<false, false, false>,
                             cudaFuncAttributeMaxDynamicSharedMemorySize, GEMM_SMEM);
        cudaFuncSetAttribute(gemm_tc<false, false, true>,
                             cudaFuncAttributeMaxDynamicSharedMemorySize, GEMM_SMEM);
        cudaFuncSetAttribute(gemm_tc<true, true, false>,
                             cudaFuncAttributeMaxDynamicSharedMemorySize, GEMM_SMEM);
        cudaFuncSetAttribute(gemm_tc<true, false, true>,
                             cudaFuncAttributeMaxDynamicSharedMemorySize, GEMM_SMEM);
        attr_done = 1;
    }

    embed_kernel<<<4096, 256>>>(idx, img, tok, pos, x);

    for (int l = 0; l < NLAYER; l++) {
        ln_kernel<<<BROWS, 256>>>(x, ln1w + l * DMODEL, ln1b + l * DMODEL, h, 0);
        gemm_tc<false, false, false><<<dim3(3 * DMODEL / 128, BROWS / 128), 256, GEMM_SMEM>>>(
            h, qkvw + (size_t)l * 3 * DMODEL * DMODEL, nullptr, nullptr, qkv,
            BROWS, 3 * DMODEL, DMODEL);
        attn_tc<<<dim3(TSEQ / 64, NHEAD, 2), 128>>>(qkv, att);
        gemm_tc<false, false, true><<<dim3(DMODEL / 128, BROWS / 128), 256, GEMM_SMEM>>>(
            att, outw + (size_t)l * DMODEL * DMODEL, nullptr, x, x,
            BROWS, DMODEL, DMODEL);
        ln_kernel<<<BROWS, 256>>>(x, ln2w + l * DMODEL, ln2b + l * DMODEL, h, 0);
        gemm_tc<true, true, false><<<dim3(DFFDIM / 128, BROWS / 128), 256, GEMM_SMEM>>>(
            h, fc1w + (size_t)l * DFFDIM * DMODEL, fc1b + l * DFFDIM, nullptr, ff,
            BROWS, DFFDIM, DMODEL);
        gemm_tc<true, false, true><<<dim3(DMODEL / 128, BROWS / 128), 256, GEMM_SMEM>>>(
            ff, fc2w + (size_t)l * DMODEL * DFFDIM, fc2b + l * DMODEL, x, x,
            BROWS, DMODEL, DFFDIM);
    }

    ln_kernel<<<MTEXT, 256>>>(x, lnfw, lnfb, hc, 1);
    gemm_tc<false, false, false><<<dim3(VOCABN / 128, MTEXT / 128), 256, GEMM_SMEM>>>(
        hc, headw, nullptr, nullptr, out, MTEXT, VOCABN, DMODEL);
}

// round 11
// speedup vs baseline: 1.2014x; 1.0142x over previous
#include <cuda_runtime.h>
#include <cuda_bf16.h>

// ---------------------------------------------------------------------------
// TinyGPT forward. All GEMM operands pre-split into bf16 hi/lo ("bf16x3"):
// weights via per-launch prepass, activations split by their producers.
// GEMM + attention mainloops are pure LDG/STS/ldmatrix/mma.
// B=2, T=2048 (NV=256 vision + 1792 text), D=1024, H=16, DH=64, L=8,
// DFF=4096, VOCAB=32000. Output: fp32 logits [2, 1792, 32000].
// ---------------------------------------------------------------------------

#define TSEQ   2048
#define NVTOK  256
#define TTEXT  1792
#define DMODEL 1024
#define DFFDIM 4096
#define NHEAD  16
#define DHEAD  64
#define NLAYER 8
#define VOCABN 32000
#define BROWS  (2 * TSEQ)
#define MTEXT  (2 * TTEXT)

// weight-split buffer offsets (elements)
#define NW_QKV  (NLAYER * 3 * DMODEL * DMODEL)
#define NW_OUT  (NLAYER * DMODEL * DMODEL)
#define NW_FC1  (NLAYER * DFFDIM * DMODEL)
#define NW_FC2  (NLAYER * DMODEL * DFFDIM)
#define NW_HEAD (VOCABN * DMODEL)
#define OFF_OUT  NW_QKV
#define OFF_FC1  (OFF_OUT + NW_OUT)
#define OFF_FC2  (OFF_FC1 + NW_FC1)
#define OFF_HEAD (OFF_FC2 + NW_FC2)
#define NW_TOT   (OFF_HEAD + NW_HEAD)

// ------------------------- scratch (device globals) ------------------------
__device__ float g_x  [BROWS * DMODEL];
__device__ float g_qkv[BROWS * 3 * DMODEL];
__device__ __nv_bfloat16 g_h_hi [BROWS * DMODEL],  g_h_lo [BROWS * DMODEL];
__device__ __nv_bfloat16 g_at_hi[BROWS * DMODEL],  g_at_lo[BROWS * DMODEL];
__device__ __nv_bfloat16 g_ff_hi[BROWS * DFFDIM],  g_ff_lo[BROWS * DFFDIM];
__device__ __nv_bfloat16 g_hc_hi[MTEXT * DMODEL],  g_hc_lo[MTEXT * DMODEL];
__device__ __nv_bfloat16 g_whi[NW_TOT], g_wlo[NW_TOT];

// ------------------------------ helpers ------------------------------------
__device__ __forceinline__ void mma16816(float c[4], const unsigned a[4],
                                         const unsigned b[2])
{
    asm volatile(
        "mma.sync.aligned.m16n8k16.row.col.f32.bf16.bf16.f32 "
        "{%0,%1,%2,%3}, {%4,%5,%6,%7}, {%8,%9}, {%0,%1,%2,%3};"
        : "+f"(c[0]), "+f"(c[1]), "+f"(c[2]), "+f"(c[3])
        : "r"(a[0]), "r"(a[1]), "r"(a[2]), "r"(a[3]), "r"(b[0]), "r"(b[1]));
}

__device__ __forceinline__ void ldm_x4(unsigned r[4], unsigned addr)
{
    asm volatile(
        "ldmatrix.sync.aligned.m8n8.x4.shared.b16 {%0,%1,%2,%3}, [%4];"
        : "=r"(r[0]), "=r"(r[1]), "=r"(r[2]), "=r"(r[3]) : "r"(addr));
}

__device__ __forceinline__ void split2(float x, float y, unsigned& hi, unsigned& lo)
{
    __nv_bfloat16 hx = __float2bfloat16(x);
    __nv_bfloat16 hy = __float2bfloat16(y);
    __nv_bfloat162 H(hx, hy);
    hi = *(unsigned*)&H;
    __nv_bfloat162 L = __floats2bfloat162_rn(x - __bfloat162float(hx),
                                             y - __bfloat162float(hy));
    lo = *(unsigned*)&L;
}

__device__ __forceinline__ void split_store4(__nv_bfloat16* hi, __nv_bfloat16* lo,
                                             float4 v)
{
    __nv_bfloat16 h0 = __float2bfloat16(v.x);
    __nv_bfloat16 h1 = __float2bfloat16(v.y);
    __nv_bfloat16 h2 = __float2bfloat16(v.z);
    __nv_bfloat16 h3 = __float2bfloat16(v.w);
    __nv_bfloat16 l0 = __float2bfloat16(v.x - __bfloat162float(h0));
    __nv_bfloat16 l1 = __float2bfloat16(v.y - __bfloat162float(h1));
    __nv_bfloat16 l2 = __float2bfloat16(v.z - __bfloat162float(h2));
    __nv_bfloat16 l3 = __float2bfloat16(v.w - __bfloat162float(h3));
    *(__nv_bfloat162*)(hi)     = __nv_bfloat162(h0, h1);
    *(__nv_bfloat162*)(hi + 2) = __nv_bfloat162(h2, h3);
    *(__nv_bfloat162*)(lo)     = __nv_bfloat162(l0, l1);
    *(__nv_bfloat162*)(lo + 2) = __nv_bfloat162(l2, l3);
}

// ----------------------- weight pre-split (per launch) ---------------------
__global__ __launch_bounds__(256)
void split_w(const float* __restrict__ src, __nv_bfloat16* __restrict__ hi,
             __nv_bfloat16* __restrict__ lo, int n4)
{
    int i = blockIdx.x * 256 + threadIdx.x;
    if (i >= n4) return;
    float4 v = ((const float4*)src)[i];
    split_store4(hi + 4 * (size_t)i, lo + 4 * (size_t)i, v);
}

// ------------------------------- embedding ---------------------------------
__global__ __launch_bounds__(256)
void embed_kernel(const int* __restrict__ idx, const float* __restrict__ img,
                  const float* __restrict__ tok, const float* __restrict__ pos,
                  float* __restrict__ x)
{
    int i = blockIdx.x * 256 + threadIdx.x;
    int d4 = (i & 255) << 2;
    int t  = (i >> 8) & (TSEQ - 1);
    int b  = i >> 19;

    float4 base;
    if (t < NVTOK) {
        base = *(const float4*)(img + ((size_t)(b * NVTOK + t) * DMODEL) + d4);
    } else {
        int tid = idx[b * TTEXT + (t - NVTOK)];
        base = *(const float4*)(tok + (size_t)tid * DMODEL + d4);
    }
    float4 p = *(const float4*)(pos + (size_t)t * DMODEL + d4);
    base.x += p.x; base.y += p.y; base.z += p.z; base.w += p.w;
    *(float4*)(x + (size_t)(b * TSEQ + t) * DMODEL + d4) = base;
}

// ------------------------------- layernorm ---------------------------------
// Writes output pre-split into bf16 hi/lo (identical values to splitting the
// fp32 result downstream).
__global__ __launch_bounds__(256)
void ln_kernel(const float* __restrict__ x, const float* __restrict__ w,
               const float* __restrict__ bias,
               __nv_bfloat16* __restrict__ ohi, __nv_bfloat16* __restrict__ olo,
               int remap)
{
    __shared__ float sh1[8];
    __shared__ float sh2[8];
    int r = blockIdx.x;
    int rin = remap ? ((r / TTEXT) * TSEQ + NVTOK + (r % TTEXT)) : r;
    int tid = threadIdx.x;

    float4 v = *(const float4*)(x + (size_t)rin * DMODEL + (tid << 2));
    float s = v.x + v.y + v.z + v.w;
    #pragma unroll
    for (int o = 16; o > 0; o >>= 1) s += __shfl_xor_sync(0xffffffffu, s, o);
    if ((tid & 31) == 0) sh1[tid >> 5] = s;
    __syncthreads();
    float tot = sh1[0] + sh1[1] + sh1[2] + sh1[3] + sh1[4] + sh1[5] + sh1[6] + sh1[7];
    float mu = tot * (1.0f / DMODEL);

    float d0 = v.x - mu, d1 = v.y - mu, d2 = v.z - mu, d3 = v.w - mu;
    float ss = d0 * d0 + d1 * d1 + d2 * d2 + d3 * d3;
    #pragma unroll
    for (int o = 16; o > 0; o >>= 1) ss += __shfl_xor_sync(0xffffffffu, ss, o);
    if ((tid & 31) == 0) sh2[tid >> 5] = ss;
    __syncthreads();
    float tot2 = sh2[0] + sh2[1] + sh2[2] + sh2[3] + sh2[4] + sh2[5] + sh2[6] + sh2[7];
    float rs = rsqrtf(tot2 * (1.0f / DMODEL) + 1e-5f);

    float4 wv = *(const float4*)(w + (tid << 2));
    float4 bv = *(const float4*)(bias + (tid << 2));
    float4 o4;
    o4.x = d0 * rs * wv.x + bv.x;
    o4.y = d1 * rs * wv.y + bv.y;
    o4.z = d2 * rs * wv.z + bv.z;
    o4.w = d3 * rs * wv.w + bv.w;
    size_t off = (size_t)r * DMODEL + (tid << 2);
    split_store4(ohi + off, olo + off, o4);
}

// ----------------------- tensor-core GEMM (bf16x3) -------------------------
// All operands pre-split bf16 hi/lo. Mainloop = LDG/STS/ldmatrix/mma only.
// BM=BN=128, BK=32, 256 threads, warp tile 64x32, double-buffered.
#define KP 40
#define BUFE (4 * 128 * KP)

template<bool BIAS, bool RELU, bool RES, bool SPLITOUT>
__global__ __launch_bounds__(256)
void gemm_tc(const __nv_bfloat16* __restrict__ Ahi, const __nv_bfloat16* __restrict__ Alo,
             const __nv_bfloat16* __restrict__ Whi, const __nv_bfloat16* __restrict__ Wlo,
             const float* __restrict__ bias, const float* __restrict__ Res,
             float* __restrict__ C, __nv_bfloat16* __restrict__ Chi,
             __nv_bfloat16* __restrict__ Clo, int M, int N, int K)
{
    extern __shared__ __nv_bfloat16 sm[];

    int n0 = blockIdx.x << 7;
    int m0 = blockIdx.y << 7;
    int tid = threadIdx.x;
    int wid = tid >> 5, lane = tid & 31;
    int grp = lane >> 2, tig = lane & 3;
    int lt = lane & 7, seg = lane >> 3;
    int wm = (wid >> 2) << 6;
    int wn = (wid & 3) << 5;

    // loaders: thread covers rows r0, r0+64; k-chunk kc (8 bf16 = 16B)
    int r0 = tid >> 2;
    int kc = (tid & 3) << 3;
    const __nv_bfloat16* Ah_g = Ahi + (size_t)(m0 + r0) * K + kc;
    const __nv_bfloat16* Al_g = Alo + (size_t)(m0 + r0) * K + kc;
    const __nv_bfloat16* Wh_g = Whi + (size_t)(n0 + r0) * K + kc;
    const __nv_bfloat16* Wl_g = Wlo + (size_t)(n0 + r0) * K + kc;
    size_t rstride = (size_t)64 * K;
    int soff0 = r0 * KP + kc;
    int soff1 = (r0 + 64) * KP + kc;

    // ldmatrix per-lane element offsets
    unsigned smbase = (unsigned)__cvta_generic_to_shared(sm);
    int aoff[4], boff[2];
    #pragma unroll
    for (int mi = 0; mi < 4; mi++)
        aoff[mi] = (wm + mi * 16 + (seg & 1) * 8 + lt) * KP + (seg >> 1) * 8;
    #pragma unroll
    for (int p = 0; p < 2; p++)
        boff[p] = (wn + (2 * p + (seg >> 1)) * 8 + lt) * KP + (seg & 1) * 8;

    float acc[4][4][4];
    #pragma unroll
    for (int mi = 0; mi < 4; mi++)
        #pragma unroll
        for (int ni = 0; ni < 4; ni++)
            #pragma unroll
            for (int q = 0; q < 4; q++) acc[mi][ni][q] = 0.f;

    uint4 sa0, sa1, sl0, sl1, sw0, sw1, sv0, sv1;
    sa0 = *(const uint4*)(Ah_g);            sa1 = *(const uint4*)(Ah_g + rstride);
    sl0 = *(const uint4*)(Al_g);            sl1 = *(const uint4*)(Al_g + rstride);
    sw0 = *(const uint4*)(Wh_g);            sw1 = *(const uint4*)(Wh_g + rstride);
    sv0 = *(const uint4*)(Wl_g);            sv1 = *(const uint4*)(Wl_g + rstride);
    {
        __nv_bfloat16* Ah = sm;           __nv_bfloat16* Al = sm + 5120;
        __nv_bfloat16* Bh = sm + 10240;   __nv_bfloat16* Bl = sm + 15360;
        *(uint4*)(Ah + soff0) = sa0; *(uint4*)(Ah + soff1) = sa1;
        *(uint4*)(Al + soff0) = sl0; *(uint4*)(Al + soff1) = sl1;
        *(uint4*)(Bh + soff0) = sw0; *(uint4*)(Bh + soff1) = sw1;
        *(uint4*)(Bl + soff0) = sv0; *(uint4*)(Bl + soff1) = sv1;
    }
    __syncthreads();

    int nk = K >> 5;
    for (int t = 0; t < nk; t++) {
        int cur = t & 1;
        bool more = (t + 1) < nk;
        if (more) {
            int kt = (t + 1) << 5;
            sa0 = *(const uint4*)(Ah_g + kt);            sa1 = *(const uint4*)(Ah_g + rstride + kt);
            sl0 = *(const uint4*)(Al_g + kt);            sl1 = *(const uint4*)(Al_g + rstride + kt);
            sw0 = *(const uint4*)(Wh_g + kt);            sw1 = *(const uint4*)(Wh_g + rstride + kt);
            sv0 = *(const uint4*)(Wl_g + kt);            sv1 = *(const uint4*)(Wl_g + rstride + kt);
        }

        unsigned Ah_b = smbase + cur * (BUFE * 2);
        unsigned Al_b = Ah_b + 5120 * 2;
        unsigned Bh_b = Ah_b + 10240 * 2;
        unsigned Bl_b = Ah_b + 15360 * 2;

        #pragma unroll
        for (int ks = 0; ks < 32; ks += 16) {
            unsigned ah[4][4], al[4][4], bhb[2][4], blb[2][4];
            #pragma unroll
            for (int mi = 0; mi < 4; mi++)
                ldm_x4(ah[mi], Ah_b + (unsigned)(aoff[mi] + ks) * 2);
            #pragma unroll
            for (int mi = 0; mi < 4; mi++)
                ldm_x4(al[mi], Al_b + (unsigned)(aoff[mi] + ks) * 2);
            #pragma unroll
            for (int p = 0; p < 2; p++)
                ldm_x4(bhb[p], Bh_b + (unsigned)(boff[p] + ks) * 2);
            #pragma unroll
            for (int p = 0; p < 2; p++)
                ldm_x4(blb[p], Bl_b + (unsigned)(boff[p] + ks) * 2);

            #pragma unroll
            for (int mi = 0; mi < 4; mi++)
                #pragma unroll
                for (int ni = 0; ni < 4; ni++) {
                    const unsigned* bh = &bhb[ni >> 1][(ni & 1) * 2];
                    const unsigned* bl = &blb[ni >> 1][(ni & 1) * 2];
                    mma16816(acc[mi][ni], ah[mi], bh);
                    mma16816(acc[mi][ni], ah[mi], bl);
                    mma16816(acc[mi][ni], al[mi], bh);
                }
        }

        if (more) {
            __nv_bfloat16* Ahn = sm + (cur ^ 1) * BUFE;
            __nv_bfloat16* Aln = Ahn + 5120;
            __nv_bfloat16* Bhn = Ahn + 10240;
            __nv_bfloat16* Bln = Ahn + 15360;
            *(uint4*)(Ahn + soff0) = sa0; *(uint4*)(Ahn + soff1) = sa1;
            *(uint4*)(Aln + soff0) = sl0; *(uint4*)(Aln + soff1) = sl1;
            *(uint4*)(Bhn + soff0) = sw0; *(uint4*)(Bhn + soff1) = sw1;
            *(uint4*)(Bln + soff0) = sv0; *(uint4*)(Bln + soff1) = sv1;
        }
        __syncthreads();
    }

    #pragma unroll
    for (int mi = 0; mi < 4; mi++) {
        #pragma unroll
        for (int ni = 0; ni < 4; ni++) {
            int row = m0 + wm + mi * 16 + grp;
            int col = n0 + wn + ni * 8 + 2 * tig;
            float2 v0 = make_float2(acc[mi][ni][0], acc[mi][ni][1]);
            float2 v1 = make_float2(acc[mi][ni][2], acc[mi][ni][3]);
            if (BIAS) {
                float2 bv = *(const float2*)(bias + col);
                v0.x += bv.x; v0.y += bv.y; v1.x += bv.x; v1.y += bv.y;
            }
            if (RELU) {
                v0.x = fmaxf(v0.x, 0.f); v0.y = fmaxf(v0.y, 0.f);
                v1.x = fmaxf(v1.x, 0.f); v1.y = fmaxf(v1.y, 0.f);
            }
            if (RES) {
                float2 r0v = *(const float2*)(Res + (size_t)row * N + col);
                float2 r1v = *(const float2*)(Res + (size_t)(row + 8) * N + col);
                v0.x += r0v.x; v0.y += r0v.y; v1.x += r1v.x; v1.y += r1v.y;
            }
            if (SPLITOUT) {
                unsigned h0, l0, h1, l1;
                split2(v0.x, v0.y, h0, l0);
                split2(v1.x, v1.y, h1, l1);
                *(unsigned*)(Chi + (size_t)row * N + col) = h0;
                *(unsigned*)(Clo + (size_t)row * N + col) = l0;
                *(unsigned*)(Chi + (size_t)(row + 8) * N + col) = h1;
                *(unsigned*)(Clo + (size_t)(row + 8) * N + col) = l1;
            } else {
                *(float2*)(C + (size_t)row * N + col) = v0;
                *(float2*)(C + (size_t)(row + 8) * N + col) = v1;
            }
        }
    }
}

// ------------------- tensor-core flash attention (bf16x3) ------------------
// Epilogue writes the attention output pre-split (bf16 hi/lo).
#define AKP 72

__global__ __launch_bounds__(128)
void attn_tc(const float* __restrict__ qkv,
             __nv_bfloat16* __restrict__ ohi, __nv_bfloat16* __restrict__ olo)
{
    const int QKVD = 3 * DMODEL;
    int qt0 = blockIdx.x << 6;
    int h = blockIdx.y, b = blockIdx.z;
    int tid = threadIdx.x;
    int warp = tid >> 5, lane = tid & 31;
    int grp = lane >> 2, tig = lane & 3;
    int lt = lane & 7, seg = lane >> 3;
    int wm = warp << 4;
    int hoff = h * DHEAD;

    __shared__ __nv_bfloat16 Ksh[64][AKP], Ksl[64][AKP];
    __shared__ __nv_bfloat16 Vth[64][AKP], Vtl[64][AKP];

    unsigned Kh_b = (unsigned)__cvta_generic_to_shared(&Ksh[0][0]);
    unsigned Kl_b = (unsigned)__cvta_generic_to_shared(&Ksl[0][0]);
    unsigned Vh_b = (unsigned)__cvta_generic_to_shared(&Vth[0][0]);
    unsigned Vl_b = (unsigned)__cvta_generic_to_shared(&Vtl[0][0]);

    int poff[4];
    #pragma unroll
    for (int p = 0; p < 4; p++)
        poff[p] = ((2 * p + (seg >> 1)) * 8 + lt) * AKP + (seg & 1) * 8;

    unsigned qh[4][4], ql[4][4];
    {
        const float* Q0 = qkv + (size_t)(b * TSEQ + qt0 + wm + grp) * QKVD + hoff;
        const float* Q1 = Q0 + (size_t)8 * QKVD;
        #pragma unroll
        for (int c = 0; c < 4; c++) {
            int k0 = 16 * c + 2 * tig;
            float2 f0 = *(const float2*)(Q0 + k0);
            float2 f1 = *(const float2*)(Q1 + k0);
            float2 f2 = *(const float2*)(Q0 + k0 + 8);
            float2 f3 = *(const float2*)(Q1 + k0 + 8);
            split2(f0.x * 0.125f, f0.y * 0.125f, qh[c][0], ql[c][0]);
            split2(f1.x * 0.125f, f1.y * 0.125f, qh[c][1], ql[c][1]);
            split2(f2.x * 0.125f, f2.y * 0.125f, qh[c][2], ql[c][2]);
            split2(f3.x * 0.125f, f3.y * 0.125f, qh[c][3], ql[c][3]);
        }
    }

    float oc[8][4];
    #pragma unroll
    for (int dt = 0; dt < 8; dt++)
        #pragma unroll
        for (int q = 0; q < 4; q++) oc[dt][q] = 0.f;
    float m0 = -1e30f, m1 = -1e30f, l0 = 0.f, l1 = 0.f;

    int qg0 = qt0 + wm + grp, qg1 = qg0 + 8;
    int ktend = (qt0 >= NVTOK) ? (qt0 + 64) : TSEQ;

    for (int kt0 = 0; kt0 < ktend; kt0 += 64) {
        #pragma unroll
        for (int i = 0; i < 8; i++) {
            int idx = tid + (i << 7);
            int key = idx >> 4, d4 = (idx & 15) << 2;
            const float* bp = qkv + (size_t)(b * TSEQ + kt0 + key) * QKVD + hoff + d4;
            float4 kv = *(const float4*)(bp + DMODEL);
            split_store4(&Ksh[key][d4], &Ksl[key][d4], kv);
            float4 vv = *(const float4*)(bp + 2 * DMODEL);
            float vf[4] = {vv.x, vv.y, vv.z, vv.w};
            #pragma unroll
            for (int j = 0; j < 4; j++) {
                __nv_bfloat16 hi = __float2bfloat16(vf[j]);
                Vth[d4 + j][key] = hi;
                Vtl[d4 + j][key] = __float2bfloat16(vf[j] - __bfloat162float(hi));
            }
        }
        __syncthreads();

        float sc[8][4];
        #pragma unroll
        for (int nt = 0; nt < 8; nt++)
            #pragma unroll
            for (int q = 0; q < 4; q++) sc[nt][q] = 0.f;

        #pragma unroll
        for (int c = 0; c < 4; c++) {
            unsigned bhb[4][4], blb[4][4];
            #pragma unroll
            for (int p = 0; p < 4; p++)
                ldm_x4(bhb[p], Kh_b + (unsigned)(poff[p] + 16 * c) * 2);
            #pragma unroll
            for (int p = 0; p < 4; p++)
                ldm_x4(blb[p], Kl_b + (unsigned)(poff[p] + 16 * c) * 2);
            #pragma unroll
            for (int nt = 0; nt < 8; nt++) {
                const unsigned* bh = &bhb[nt >> 1][(nt & 1) * 2];
                const unsigned* bl = &blb[nt >> 1][(nt & 1) * 2];
                mma16816(sc[nt], qh[c], bh);
                mma16816(sc[nt], qh[c], bl);
                mma16816(sc[nt], ql[c], bh);
            }
        }

        #pragma unroll
        for (int nt = 0; nt < 8; nt++) {
            int kg0 = kt0 + nt * 8 + 2 * tig;
            int kg1 = kg0 + 1;
            if (!((qg0 < NVTOK) || (kg0 <= qg0))) sc[nt][0] = -1e30f;
            if (!((qg0 < NVTOK) || (kg1 <= qg0))) sc[nt][1] = -1e30f;
            if (!((qg1 < NVTOK) || (kg0 <= qg1))) sc[nt][2] = -1e30f;
            if (!((qg1 < NVTOK) || (kg1 <= qg1))) sc[nt][3] = -1e30f;
        }

        float mx0 = -1e30f, mx1 = -1e30f;
        #pragma unroll
        for (int nt = 0; nt < 8; nt++) {
            mx0 = fmaxf(mx0, fmaxf(sc[nt][0], sc[nt][1]));
            mx1 = fmaxf(mx1, fmaxf(sc[nt][2], sc[nt][3]));
        }
        mx0 = fmaxf(mx0, __shfl_xor_sync(0xffffffffu, mx0, 1));
        mx0 = fmaxf(mx0, __shfl_xor_sync(0xffffffffu, mx0, 2));
        mx1 = fmaxf(mx1, __shfl_xor_sync(0xffffffffu, mx1, 1));
        mx1 = fmaxf(mx1, __shfl_xor_sync(0xffffffffu, mx1, 2));
        float mn0 = fmaxf(m0, mx0), mn1 = fmaxf(m1, mx1);
        float al0 = __expf(m0 - mn0), al1 = __expf(m1 - mn1);
        m0 = mn0; m1 = mn1;

        float sum0 = 0.f, sum1 = 0.f;
        #pragma unroll
        for (int nt = 0; nt < 8; nt++) {
            sc[nt][0] = __expf(sc[nt][0] - mn0); sum0 += sc[nt][0];
            sc[nt][1] = __expf(sc[nt][1] - mn0); sum0 += sc[nt][1];
            sc[nt][2] = __expf(sc[nt][2] - mn1); sum1 += sc[nt][2];
            sc[nt][3] = __expf(sc[nt][3] - mn1); sum1 += sc[nt][3];
        }
        sum0 += __shfl_xor_sync(0xffffffffu, sum0, 1);
        sum0 += __shfl_xor_sync(0xffffffffu, sum0, 2);
        sum1 += __shfl_xor_sync(0xffffffffu, sum1, 1);
        sum1 += __shfl_xor_sync(0xffffffffu, sum1, 2);
        l0 = l0 * al0 + sum0;
        l1 = l1 * al1 + sum1;

        #pragma unroll
        for (int dt = 0; dt < 8; dt++) {
            oc[dt][0] *= al0; oc[dt][1] *= al0;
            oc[dt][2] *= al1; oc[dt][3] *= al1;
        }

        unsigned ph[4][4], pl[4][4];
        #pragma unroll
        for (int c = 0; c < 4; c++) {
            split2(sc[2 * c][0],     sc[2 * c][1],     ph[c][0], pl[c][0]);
            split2(sc[2 * c][2],     sc[2 * c][3],     ph[c][1], pl[c][1]);
            split2(sc[2 * c + 1][0], sc[2 * c + 1][1], ph[c][2], pl[c][2]);
            split2(sc[2 * c + 1][2], sc[2 * c + 1][3], ph[c][3], pl[c][3]);
        }

        #pragma unroll
        for (int c = 0; c < 4; c++) {
            unsigned bhb[4][4], blb[4][4];
            #pragma unroll
            for (int p = 0; p < 4; p++)
                ldm_x4(bhb[p], Vh_b + (unsigned)(poff[p] + 16 * c) * 2);
            #pragma unroll
            for (int p = 0; p < 4; p++)
                ldm_x4(blb[p], Vl_b + (unsigned)(poff[p] + 16 * c) * 2);
            #pragma unroll
            for (int dt = 0; dt < 8; dt++) {
                const unsigned* bh = &bhb[dt >> 1][(dt & 1) * 2];
                const unsigned* bl = &blb[dt >> 1][(dt & 1) * 2];
                mma16816(oc[dt], ph[c], bh);
                mma16816(oc[dt], ph[c], bl);
                mma16816(oc[dt], pl[c], bh);
            }
        }
        __syncthreads();
    }

    float inv0 = 1.f / l0, inv1 = 1.f / l1;
    size_t base0 = (size_t)(b * TSEQ + qg0) * DMODEL + hoff;
    size_t base1 = (size_t)(b * TSEQ + qg1) * DMODEL + hoff;
    #pragma unroll
    for (int dt = 0; dt < 8; dt++) {
        int dcol = dt * 8 + 2 * tig;
        unsigned h0, l0p, h1, l1p;
        split2(oc[dt][0] * inv0, oc[dt][1] * inv0, h0, l0p);
        split2(oc[dt][2] * inv1, oc[dt][3] * inv1, h1, l1p);
        *(unsigned*)(ohi + base0 + dcol) = h0;
        *(unsigned*)(olo + base0 + dcol) = l0p;
        *(unsigned*)(ohi + base1 + dcol) = h1;
        *(unsigned*)(olo + base1 + dcol) = l1p;
    }
}

// -------------------------------- launcher ---------------------------------
#define GEMM_SMEM 81920

extern "C" void kernel_launch(void* const* d_in, const int* in_sizes, int n_in,
                              void* d_out, int out_size)
{
    (void)in_sizes; (void)n_in; (void)out_size;
    const int*   idx   = (const int*)  d_in[0];
    const float* img   = (const float*)d_in[1];
    const float* tok   = (const float*)d_in[2];
    const float* pos   = (const float*)d_in[3];
    const float* ln1w  = (const float*)d_in[4];
    const float* ln1b  = (const float*)d_in[5];
    const float* qkvw  = (const float*)d_in[6];
    const float* outw  = (const float*)d_in[7];
    const float* ln2w  = (const float*)d_in[8];
    const float* ln2b  = (const float*)d_in[9];
    const float* fc1w  = (const float*)d_in[10];
    const float* fc1b  = (const float*)d_in[11];
    const float* fc2w  = (const float*)d_in[12];
    const float* fc2b  = (const float*)d_in[13];
    const float* lnfw  = (const float*)d_in[14];
    const float* lnfb  = (const float*)d_in[15];
    const float* headw = (const float*)d_in[16];
    float* out = (float*)d_out;

    float *x, *qkv;
    __nv_bfloat16 *hhi, *hlo, *athi, *atlo, *ffhi, *fflo, *hchi, *hclo, *whi, *wlo;
    cudaGetSymbolAddress((void**)&x,    g_x);
    cudaGetSymbolAddress((void**)&qkv,  g_qkv);
    cudaGetSymbolAddress((void**)&hhi,  g_h_hi);
    cudaGetSymbolAddress((void**)&hlo,  g_h_lo);
    cudaGetSymbolAddress((void**)&athi, g_at_hi);
    cudaGetSymbolAddress((void**)&atlo, g_at_lo);
    cudaGetSymbolAddress((void**)&ffhi, g_ff_hi);
    cudaGetSymbolAddress((void**)&fflo, g_ff_lo);
    cudaGetSymbolAddress((void**)&hchi, g_hc_hi);
    cudaGetSymbolAddress((void**)&hclo, g_hc_lo);
    cudaGetSymbolAddress((void**)&whi,  g_whi);
    cudaGetSymbolAddress((void**)&wlo,  g_wlo);

    static int attr_done = 0;
    if (!attr_done) {
        cudaFuncSetAttribute(gemm_tc<false, false, false, false>,
                             cudaFuncAttributeMaxDynamicSharedMemorySize, GEMM_SMEM);
        cudaFuncSetAttribute(gemm_tc<false, false, true, false>,
                             cudaFuncAttributeMaxDynamicSharedMemorySize, GEMM_SMEM);
        cudaFuncSetAttribute(gemm_tc<true, true, false, true>,
                             cudaFuncAttributeMaxDynamicSharedMemorySize, GEMM_SMEM);
        cudaFuncSetAttribute(gemm_tc<true, false, true, false>,
                             cudaFuncAttributeMaxDynamicSharedMemorySize, GEMM_SMEM);
        attr_done = 1;
    }

    // weight pre-split (graph-capturable, deterministic)
    split_w<<<(NW_QKV / 4 + 255) / 256, 256>>>(qkvw,  whi,            wlo,            NW_QKV / 4);
    split_w<<<(NW_OUT / 4 + 255) / 256, 256>>>(outw,  whi + OFF_OUT,  wlo + OFF_OUT,  NW_OUT / 4);
    split_w<<<(NW_FC1 / 4 + 255) / 256, 256>>>(fc1w,  whi + OFF_FC1,  wlo + OFF_FC1,  NW_FC1 / 4);
    split_w<<<(NW_FC2 / 4 + 255) / 256, 256>>>(fc2w,  whi + OFF_FC2,  wlo + OFF_FC2,  NW_FC2 / 4);
    split_w<<<(NW_HEAD / 4 + 255) / 256, 256>>>(headw, whi + OFF_HEAD, wlo + OFF_HEAD, NW_HEAD / 4);

    embed_kernel<<<4096, 256>>>(idx, img, tok, pos, x);

    for (int l = 0; l < NLAYER; l++) {
        size_t oq = (size_t)l * 3 * DMODEL * DMODEL;
        size_t oo = OFF_OUT + (size_t)l * DMODEL * DMODEL;
        size_t o1 = OFF_FC1 + (size_t)l * DFFDIM * DMODEL;
        size_t o2 = OFF_FC2 + (size_t)l * DMODEL * DFFDIM;

        ln_kernel<<<BROWS, 256>>>(x, ln1w + l * DMODEL, ln1b + l * DMODEL, hhi, hlo, 0);
        gemm_tc<false, false, false, false><<<dim3(3 * DMODEL / 128, BROWS / 128), 256, GEMM_SMEM>>>(
            hhi, hlo, whi + oq, wlo + oq, nullptr, nullptr, qkv, nullptr, nullptr,
            BROWS, 3 * DMODEL, DMODEL);
        attn_tc<<<dim3(TSEQ / 64, NHEAD, 2), 128>>>(qkv, athi, atlo);
        gemm_tc<false, false, true, false><<<dim3(DMODEL / 128, BROWS / 128), 256, GEMM_SMEM>>>(
            athi, atlo, whi + oo, wlo + oo, nullptr, x, x, nullptr, nullptr,
            BROWS, DMODEL, DMODEL);
        ln_kernel<<<BROWS, 256>>>(x, ln2w + l * DMODEL, ln2b + l * DMODEL, hhi, hlo, 0);
        gemm_tc<true, true, false, true><<<dim3(DFFDIM / 128, BROWS / 128), 256, GEMM_SMEM>>>(
            hhi, hlo, whi + o1, wlo + o1, fc1b + l * DFFDIM, nullptr, nullptr, ffhi, fflo,
            BROWS, DFFDIM, DMODEL);
        gemm_tc<true, false, true, false><<<dim3(DMODEL / 128, BROWS / 128), 256, GEMM_SMEM>>>(
            ffhi, fflo, whi + o2, wlo + o2, fc2b + l * DMODEL, x, x, nullptr, nullptr,
            BROWS, DMODEL, DFFDIM);
    }

    ln_kernel<<<MTEXT, 256>>>(x, lnfw, lnfb, hchi, hclo, 1);
    gemm_tc<false, false, false, false><<<dim3(VOCABN / 128, MTEXT / 128), 256, GEMM_SMEM>>>(
        hchi, hclo, whi + OFF_HEAD, wlo + OFF_HEAD, nullptr, nullptr, out, nullptr, nullptr,
        MTEXT, VOCABN, DMODEL);
}

// round 16
// speedup vs baseline: 1.2194x; 1.0150x over previous
#include <cuda_runtime.h>
#include <cuda_bf16.h>
#include <cstdint>

// ---------------------------------------------------------------------------
// TinyGPT forward. GEMMs: mma.sync bf16x3, 128x256 CTA tile, 64x64 warp tile,
// cp.async 2-stage pipeline. Attention: mma.sync bf16x3 flash. LN/embed SIMT.
// B=2, T=2048 (NV=256 vision + 1792 text), D=1024, H=16, DH=64, L=8,
// DFF=4096, VOCAB=32000. Output: fp32 logits [2, 1792, 32000].
// ---------------------------------------------------------------------------

#define TSEQ   2048
#define NVTOK  256
#define TTEXT  1792
#define DMODEL 1024
#define DFFDIM 4096
#define NHEAD  16
#define DHEAD  64
#define NLAYER 8
#define VOCABN 32000
#define BROWS  (2 * TSEQ)
#define MTEXT  (2 * TTEXT)

#define NW_QKV  (NLAYER * 3 * DMODEL * DMODEL)
#define NW_OUT  (NLAYER * DMODEL * DMODEL)
#define NW_FC1  (NLAYER * DFFDIM * DMODEL)
#define NW_FC2  (NLAYER * DMODEL * DFFDIM)
#define NW_HEAD (VOCABN * DMODEL)
#define OFF_OUT  NW_QKV
#define OFF_FC1  (OFF_OUT + NW_OUT)
#define OFF_FC2  (OFF_FC1 + NW_FC1)
#define OFF_HEAD (OFF_FC2 + NW_FC2)
#define NW_TOT   (OFF_HEAD + NW_HEAD)

// ------------------------- scratch (device globals) ------------------------
__device__ float g_x  [BROWS * DMODEL];
__device__ float g_qkv[BROWS * 3 * DMODEL];
__device__ __nv_bfloat16 g_h_hi [BROWS * DMODEL],  g_h_lo [BROWS * DMODEL];
__device__ __nv_bfloat16 g_at_hi[BROWS * DMODEL],  g_at_lo[BROWS * DMODEL];
__device__ __nv_bfloat16 g_ff_hi[BROWS * DFFDIM],  g_ff_lo[BROWS * DFFDIM];
__device__ __nv_bfloat16 g_hc_hi[MTEXT * DMODEL],  g_hc_lo[MTEXT * DMODEL];
__device__ __nv_bfloat16 g_whi[NW_TOT], g_wlo[NW_TOT];

// ------------------------------ helpers ------------------------------------
__device__ __forceinline__ void mma16816(float c[4], const unsigned a[4],
                                         const unsigned b[2])
{
    asm volatile(
        "mma.sync.aligned.m16n8k16.row.col.f32.bf16.bf16.f32 "
        "{%0,%1,%2,%3}, {%4,%5,%6,%7}, {%8,%9}, {%0,%1,%2,%3};"
        : "+f"(c[0]), "+f"(c[1]), "+f"(c[2]), "+f"(c[3])
        : "r"(a[0]), "r"(a[1]), "r"(a[2]), "r"(a[3]), "r"(b[0]), "r"(b[1]));
}
__device__ __forceinline__ void ldm_x4(unsigned r[4], unsigned addr)
{
    asm volatile(
        "ldmatrix.sync.aligned.m8n8.x4.shared.b16 {%0,%1,%2,%3}, [%4];"
        : "=r"(r[0]), "=r"(r[1]), "=r"(r[2]), "=r"(r[3]) : "r"(addr));
}
__device__ __forceinline__ void split2(float x, float y, unsigned& hi, unsigned& lo)
{
    __nv_bfloat16 hx = __float2bfloat16(x);
    __nv_bfloat16 hy = __float2bfloat16(y);
    __nv_bfloat162 H(hx, hy);
    hi = *(unsigned*)&H;
    __nv_bfloat162 L = __floats2bfloat162_rn(x - __bfloat162float(hx),
                                             y - __bfloat162float(hy));
    lo = *(unsigned*)&L;
}
__device__ __forceinline__ void split_store4(__nv_bfloat16* hi, __nv_bfloat16* lo,
                                             float4 v)
{
    __nv_bfloat16 h0 = __float2bfloat16(v.x);
    __nv_bfloat16 h1 = __float2bfloat16(v.y);
    __nv_bfloat16 h2 = __float2bfloat16(v.z);
    __nv_bfloat16 h3 = __float2bfloat16(v.w);
    __nv_bfloat16 l0 = __float2bfloat16(v.x - __bfloat162float(h0));
    __nv_bfloat16 l1 = __float2bfloat16(v.y - __bfloat162float(h1));
    __nv_bfloat16 l2 = __float2bfloat16(v.z - __bfloat162float(h2));
    __nv_bfloat16 l3 = __float2bfloat16(v.w - __bfloat162float(h3));
    *(__nv_bfloat162*)(hi)     = __nv_bfloat162(h0, h1);
    *(__nv_bfloat162*)(hi + 2) = __nv_bfloat162(h2, h3);
    *(__nv_bfloat162*)(lo)     = __nv_bfloat162(l0, l1);
    *(__nv_bfloat162*)(lo + 2) = __nv_bfloat162(l2, l3);
}

#define CP_ASYNC16(saddr, gptr) \
    asm volatile("cp.async.ca.shared.global [%0], [%1], 16;" \
                 :: "r"(saddr), "l"(gptr) : "memory")
#define CP_COMMIT() asm volatile("cp.async.commit_group;" ::: "memory")
#define CP_WAIT(n)  asm volatile("cp.async.wait_group %0;" :: "n"(n) : "memory")

// ----------------------- weight pre-split (per launch) ---------------------
__global__ __launch_bounds__(256)
void split_w(const float* __restrict__ src, __nv_bfloat16* __restrict__ hi,
             __nv_bfloat16* __restrict__ lo, int n4)
{
    int i = blockIdx.x * 256 + threadIdx.x;
    if (i >= n4) return;
    float4 v = ((const float4*)src)[i];
    split_store4(hi + 4 * (size_t)i, lo + 4 * (size_t)i, v);
}

// ------------------------------- embedding ---------------------------------
__global__ __launch_bounds__(256)
void embed_kernel(const int* __restrict__ idx, const float* __restrict__ img,
                  const float* __restrict__ tok, const float* __restrict__ pos,
                  float* __restrict__ x)
{
    int i = blockIdx.x * 256 + threadIdx.x;
    int d4 = (i & 255) << 2;
    int t  = (i >> 8) & (TSEQ - 1);
    int b  = i >> 19;

    float4 base;
    if (t < NVTOK) {
        base = *(const float4*)(img + ((size_t)(b * NVTOK + t) * DMODEL) + d4);
    } else {
        int tid = idx[b * TTEXT + (t - NVTOK)];
        base = *(const float4*)(tok + (size_t)tid * DMODEL + d4);
    }
    float4 p = *(const float4*)(pos + (size_t)t * DMODEL + d4);
    base.x += p.x; base.y += p.y; base.z += p.z; base.w += p.w;
    *(float4*)(x + (size_t)(b * TSEQ + t) * DMODEL + d4) = base;
}

// ------------------------------- layernorm ---------------------------------
__global__ __launch_bounds__(256)
void ln_kernel(const float* __restrict__ x, const float* __restrict__ w,
               const float* __restrict__ bias,
               __nv_bfloat16* __restrict__ ohi, __nv_bfloat16* __restrict__ olo,
               int remap)
{
    __shared__ float sh1[8];
    __shared__ float sh2[8];
    int r = blockIdx.x;
    int rin = remap ? ((r / TTEXT) * TSEQ + NVTOK + (r % TTEXT)) : r;
    int tid = threadIdx.x;

    float4 v = *(const float4*)(x + (size_t)rin * DMODEL + (tid << 2));
    float s = v.x + v.y + v.z + v.w;
    #pragma unroll
    for (int o = 16; o > 0; o >>= 1) s += __shfl_xor_sync(0xffffffffu, s, o);
    if ((tid & 31) == 0) sh1[tid >> 5] = s;
    __syncthreads();
    float tot = sh1[0] + sh1[1] + sh1[2] + sh1[3] + sh1[4] + sh1[5] + sh1[6] + sh1[7];
    float mu = tot * (1.0f / DMODEL);

    float d0 = v.x - mu, d1 = v.y - mu, d2 = v.z - mu, d3 = v.w - mu;
    float ss = d0 * d0 + d1 * d1 + d2 * d2 + d3 * d3;
    #pragma unroll
    for (int o = 16; o > 0; o >>= 1) ss += __shfl_xor_sync(0xffffffffu, ss, o);
    if ((tid & 31) == 0) sh2[tid >> 5] = ss;
    __syncthreads();
    float tot2 = sh2[0] + sh2[1] + sh2[2] + sh2[3] + sh2[4] + sh2[5] + sh2[6] + sh2[7];
    float rs = rsqrtf(tot2 * (1.0f / DMODEL) + 1e-5f);

    float4 wv = *(const float4*)(w + (tid << 2));
    float4 bv = *(const float4*)(bias + (tid << 2));
    float4 o4;
    o4.x = d0 * rs * wv.x + bv.x;
    o4.y = d1 * rs * wv.y + bv.y;
    o4.z = d2 * rs * wv.z + bv.z;
    o4.w = d3 * rs * wv.w + bv.w;
    size_t off = (size_t)r * DMODEL + (tid << 2);
    split_store4(ohi + off, olo + off, o4);
}

// ----------------------- tensor-core GEMM (bf16x3) -------------------------
// All operands pre-split bf16 hi/lo. CTA tile 128x256, BK=32, 256 thr, 8 warps,
// warp tile 64x64. cp.async 2-stage pipeline. Requires M%128, N%256, K%32.
#define KP 40
// stage layout (bf16 elems): Ah[0,5120) Al[5120,10240) Bh[10240,20480) Bl[20480,30720)
#define BUFE 30720
#define GEMM_SMEM (2 * BUFE * 2)

template<bool BIAS, bool RELU, bool RES, bool SPLITOUT>
__global__ __launch_bounds__(256)
void gemm_tc(const __nv_bfloat16* __restrict__ Ahi, const __nv_bfloat16* __restrict__ Alo,
             const __nv_bfloat16* __restrict__ Whi, const __nv_bfloat16* __restrict__ Wlo,
             const float* __restrict__ bias, const float* __restrict__ Res,
             float* __restrict__ C, __nv_bfloat16* __restrict__ Chi,
             __nv_bfloat16* __restrict__ Clo, int M, int N, int K)
{
    extern __shared__ __nv_bfloat16 sm[];

    int n0 = blockIdx.x << 8;
    int m0 = blockIdx.y << 7;
    int tid = threadIdx.x;
    int wid = tid >> 5, lane = tid & 31;
    int grp = lane >> 2, tig = lane & 3;
    int lt = lane & 7, seg = lane >> 3;
    int wm = (wid >> 2) << 6;     // 0 or 64
    int wn = (wid & 3) << 6;      // 0,64,128,192

    // loader mapping: rows r0 + 64j, k-chunk kc (8 bf16 = 16B)
    int r0 = tid >> 2;            // 0..63
    int kc = (tid & 3) << 3;      // 0,8,16,24
    const __nv_bfloat16* Ah_g = Ahi + (size_t)(m0 + r0) * K + kc;
    const __nv_bfloat16* Al_g = Alo + (size_t)(m0 + r0) * K + kc;
    const __nv_bfloat16* Bh_g = Whi + (size_t)(n0 + r0) * K + kc;
    const __nv_bfloat16* Bl_g = Wlo + (size_t)(n0 + r0) * K + kc;
    size_t rs64 = (size_t)64 * K;
    unsigned smbase = (unsigned)__cvta_generic_to_shared(sm);
    unsigned soff = (unsigned)(r0 * KP + kc) * 2;

    // ldmatrix per-lane element offsets
    int aoff[4], boff[4];
    #pragma unroll
    for (int mi = 0; mi < 4; mi++)
        aoff[mi] = (wm + mi * 16 + (seg & 1) * 8 + lt) * KP + (seg >> 1) * 8;
    #pragma unroll
    for (int p = 0; p < 4; p++)
        boff[p] = (wn + (2 * p + (seg >> 1)) * 8 + lt) * KP + (seg & 1) * 8;

    float acc[4][8][4];
    #pragma unroll
    for (int mi = 0; mi < 4; mi++)
        #pragma unroll
        for (int ni = 0; ni < 8; ni++)
            #pragma unroll
            for (int q = 0; q < 4; q++) acc[mi][ni][q] = 0.f;

    // stage issue: 12 cp.async per thread
    auto issue = [&](int buf, int kt) {
        unsigned sb = smbase + buf * (BUFE * 2);
        #pragma unroll
        for (int j = 0; j < 2; j++) {
            unsigned so = sb + soff + j * (64 * KP * 2);
            CP_ASYNC16(so,         Ah_g + rs64 * j + kt);
            CP_ASYNC16(so + 10240, Al_g + rs64 * j + kt);
        }
        #pragma unroll
        for (int j = 0; j < 4; j++) {
            unsigned so = sb + soff + j * (64 * KP * 2);
            CP_ASYNC16(so + 20480, Bh_g + rs64 * j + kt);
            CP_ASYNC16(so + 40960, Bl_g + rs64 * j + kt);
        }
        CP_COMMIT();
    };

    issue(0, 0);

    int nt = K >> 5;
    for (int t = 0; t < nt; t++) {
        int cur = t & 1;
        if (t + 1 < nt) {
            issue(cur ^ 1, (t + 1) << 5);
            CP_WAIT(1);
        } else {
            CP_WAIT(0);
        }
        __syncthreads();

        unsigned Ah_b = smbase + cur * (BUFE * 2);
        unsigned Al_b = Ah_b + 10240;
        unsigned Bh_b = Ah_b + 20480;
        unsigned Bl_b = Ah_b + 40960;

        #pragma unroll
        for (int ks = 0; ks < 32; ks += 16) {
            unsigned ah[4][4], al[4][4], bhb[4][4], blb[4][4];
            #pragma unroll
            for (int mi = 0; mi < 4; mi++)
                ldm_x4(ah[mi], Ah_b + (unsigned)(aoff[mi] + ks) * 2);
            #pragma unroll
            for (int mi = 0; mi < 4; mi++)
                ldm_x4(al[mi], Al_b + (unsigned)(aoff[mi] + ks) * 2);
            #pragma unroll
            for (int p = 0; p < 4; p++)
                ldm_x4(bhb[p], Bh_b + (unsigned)(boff[p] + ks) * 2);
            #pragma unroll
            for (int p = 0; p < 4; p++)
                ldm_x4(blb[p], Bl_b + (unsigned)(boff[p] + ks) * 2);

            #pragma unroll
            for (int mi = 0; mi < 4; mi++)
                #pragma unroll
                for (int ni = 0; ni < 8; ni++) {
                    const unsigned* bh = &bhb[ni >> 1][(ni & 1) * 2];
                    const unsigned* bl = &blb[ni >> 1][(ni & 1) * 2];
                    mma16816(acc[mi][ni], ah[mi], bh);
                    mma16816(acc[mi][ni], ah[mi], bl);
                    mma16816(acc[mi][ni], al[mi], bh);
                }
        }
        __syncthreads();
    }

    #pragma unroll
    for (int mi = 0; mi < 4; mi++) {
        #pragma unroll
        for (int ni = 0; ni < 8; ni++) {
            int row = m0 + wm + mi * 16 + grp;
            int col = n0 + wn + ni * 8 + 2 * tig;
            float2 v0 = make_float2(acc[mi][ni][0], acc[mi][ni][1]);
            float2 v1 = make_float2(acc[mi][ni][2], acc[mi][ni][3]);
            if (BIAS) {
                float2 bv = *(const float2*)(bias + col);
                v0.x += bv.x; v0.y += bv.y; v1.x += bv.x; v1.y += bv.y;
            }
            if (RELU) {
                v0.x = fmaxf(v0.x, 0.f); v0.y = fmaxf(v0.y, 0.f);
                v1.x = fmaxf(v1.x, 0.f); v1.y = fmaxf(v1.y, 0.f);
            }
            if (RES) {
                float2 r0v = *(const float2*)(Res + (size_t)row * N + col);
                float2 r1v = *(const float2*)(Res + (size_t)(row + 8) * N + col);
                v0.x += r0v.x; v0.y += r0v.y; v1.x += r1v.x; v1.y += r1v.y;
            }
            if (SPLITOUT) {
                unsigned h0, l0, h1, l1;
                split2(v0.x, v0.y, h0, l0);
                split2(v1.x, v1.y, h1, l1);
                *(unsigned*)(Chi + (size_t)row * N + col) = h0;
                *(unsigned*)(Clo + (size_t)row * N + col) = l0;
                *(unsigned*)(Chi + (size_t)(row + 8) * N + col) = h1;
                *(unsigned*)(Clo + (size_t)(row + 8) * N + col) = l1;
            } else {
                *(float2*)(C + (size_t)row * N + col) = v0;
                *(float2*)(C + (size_t)(row + 8) * N + col) = v1;
            }
        }
    }
}

// ------------------- tensor-core flash attention (bf16x3) ------------------
#define AKP 72

__global__ __launch_bounds__(128)
void attn_tc(const float* __restrict__ qkv,
             __nv_bfloat16* __restrict__ ohi, __nv_bfloat16* __restrict__ olo)
{
    const int QKVD = 3 * DMODEL;
    int qt0 = blockIdx.x << 6;
    int h = blockIdx.y, b = blockIdx.z;
    int tid = threadIdx.x;
    int warp = tid >> 5, lane = tid & 31;
    int grp = lane >> 2, tig = lane & 3;
    int lt = lane & 7, seg = lane >> 3;
    int wm = warp << 4;
    int hoff = h * DHEAD;

    __shared__ __nv_bfloat16 Ksh[64][AKP], Ksl[64][AKP];
    __shared__ __nv_bfloat16 Vth[64][AKP], Vtl[64][AKP];

    unsigned Kh_b = (unsigned)__cvta_generic_to_shared(&Ksh[0][0]);
    unsigned Kl_b = (unsigned)__cvta_generic_to_shared(&Ksl[0][0]);
    unsigned Vh_b = (unsigned)__cvta_generic_to_shared(&Vth[0][0]);
    unsigned Vl_b = (unsigned)__cvta_generic_to_shared(&Vtl[0][0]);

    int poff[4];
    #pragma unroll
    for (int p = 0; p < 4; p++)
        poff[p] = ((2 * p + (seg >> 1)) * 8 + lt) * AKP + (seg & 1) * 8;

    unsigned qh[4][4], ql[4][4];
    {
        const float* Q0 = qkv + (size_t)(b * TSEQ + qt0 + wm + grp) * QKVD + hoff;
        const float* Q1 = Q0 + (size_t)8 * QKVD;
        #pragma unroll
        for (int c = 0; c < 4; c++) {
            int k0 = 16 * c + 2 * tig;
            float2 f0 = *(const float2*)(Q0 + k0);
            float2 f1 = *(const float2*)(Q1 + k0);
            float2 f2 = *(const float2*)(Q0 + k0 + 8);
            float2 f3 = *(const float2*)(Q1 + k0 + 8);
            split2(f0.x * 0.125f, f0.y * 0.125f, qh[c][0], ql[c][0]);
            split2(f1.x * 0.125f, f1.y * 0.125f, qh[c][1], ql[c][1]);
            split2(f2.x * 0.125f, f2.y * 0.125f, qh[c][2], ql[c][2]);
            split2(f3.x * 0.125f, f3.y * 0.125f, qh[c][3], ql[c][3]);
        }
    }

    float oc[8][4];
    #pragma unroll
    for (int dt = 0; dt < 8; dt++)
        #pragma unroll
        for (int q = 0; q < 4; q++) oc[dt][q] = 0.f;
    float m0 = -1e30f, m1 = -1e30f, l0 = 0.f, l1 = 0.f;

    int qg0 = qt0 + wm + grp, qg1 = qg0 + 8;
    int ktend = (qt0 >= NVTOK) ? (qt0 + 64) : TSEQ;

    for (int kt0 = 0; kt0 < ktend; kt0 += 64) {
        #pragma unroll
        for (int i = 0; i < 8; i++) {
            int idx = tid + (i << 7);
            int key = idx >> 4, d4 = (idx & 15) << 2;
            const float* bp = qkv + (size_t)(b * TSEQ + kt0 + key) * QKVD + hoff + d4;
            float4 kv = *(const float4*)(bp + DMODEL);
            split_store4(&Ksh[key][d4], &Ksl[key][d4], kv);
            float4 vv = *(const float4*)(bp + 2 * DMODEL);
            float vf[4] = {vv.x, vv.y, vv.z, vv.w};
            #pragma unroll
            for (int j = 0; j < 4; j++) {
                __nv_bfloat16 hi = __float2bfloat16(vf[j]);
                Vth[d4 + j][key] = hi;
                Vtl[d4 + j][key] = __float2bfloat16(vf[j] - __bfloat162float(hi));
            }
        }
        __syncthreads();

        float sc[8][4];
        #pragma unroll
        for (int nt = 0; nt < 8; nt++)
            #pragma unroll
            for (int q = 0; q < 4; q++) sc[nt][q] = 0.f;

        #pragma unroll
        for (int c = 0; c < 4; c++) {
            unsigned bhb[4][4], blb[4][4];
            #pragma unroll
            for (int p = 0; p < 4; p++)
                ldm_x4(bhb[p], Kh_b + (unsigned)(poff[p] + 16 * c) * 2);
            #pragma unroll
            for (int p = 0; p < 4; p++)
                ldm_x4(blb[p], Kl_b + (unsigned)(poff[p] + 16 * c) * 2);
            #pragma unroll
            for (int nt = 0; nt < 8; nt++) {
                const unsigned* bh = &bhb[nt >> 1][(nt & 1) * 2];
                const unsigned* bl = &blb[nt >> 1][(nt & 1) * 2];
                mma16816(sc[nt], qh[c], bh);
                mma16816(sc[nt], qh[c], bl);
                mma16816(sc[nt], ql[c], bh);
            }
        }

        #pragma unroll
        for (int nt = 0; nt < 8; nt++) {
            int kg0 = kt0 + nt * 8 + 2 * tig;
            int kg1 = kg0 + 1;
            if (!((qg0 < NVTOK) || (kg0 <= qg0))) sc[nt][0] = -1e30f;
            if (!((qg0 < NVTOK) || (kg1 <= qg0))) sc[nt][1] = -1e30f;
            if (!((qg1 < NVTOK) || (kg0 <= qg1))) sc[nt][2] = -1e30f;
            if (!((qg1 < NVTOK) || (kg1 <= qg1))) sc[nt][3] = -1e30f;
        }

        float mx0 = -1e30f, mx1 = -1e30f;
        #pragma unroll
        for (int nt = 0; nt < 8; nt++) {
            mx0 = fmaxf(mx0, fmaxf(sc[nt][0], sc[nt][1]));
            mx1 = fmaxf(mx1, fmaxf(sc[nt][2], sc[nt][3]));
        }
        mx0 = fmaxf(mx0, __shfl_xor_sync(0xffffffffu, mx0, 1));
        mx0 = fmaxf(mx0, __shfl_xor_sync(0xffffffffu, mx0, 2));
        mx1 = fmaxf(mx1, __shfl_xor_sync(0xffffffffu, mx1, 1));
        mx1 = fmaxf(mx1, __shfl_xor_sync(0xffffffffu, mx1, 2));
        float mn0 = fmaxf(m0, mx0), mn1 = fmaxf(m1, mx1);
        float al0 = __expf(m0 - mn0), al1 = __expf(m1 - mn1);
        m0 = mn0; m1 = mn1;

        float sum0 = 0.f, sum1 = 0.f;
        #pragma unroll
        for (int nt = 0; nt < 8; nt++) {
            sc[nt][0] = __expf(sc[nt][0] - mn0); sum0 += sc[nt][0];
            sc[nt][1] = __expf(sc[nt][1] - mn0); sum0 += sc[nt][1];
            sc[nt][2] = __expf(sc[nt][2] - mn1); sum1 += sc[nt][2];
            sc[nt][3] = __expf(sc[nt][3] - mn1); sum1 += sc[nt][3];
        }
        sum0 += __shfl_xor_sync(0xffffffffu, sum0, 1);
        sum0 += __shfl_xor_sync(0xffffffffu, sum0, 2);
        sum1 += __shfl_xor_sync(0xffffffffu, sum1, 1);
        sum1 += __shfl_xor_sync(0xffffffffu, sum1, 2);
        l0 = l0 * al0 + sum0;
        l1 = l1 * al1 + sum1;

        #pragma unroll
        for (int dt = 0; dt < 8; dt++) {
            oc[dt][0] *= al0; oc[dt][1] *= al0;
            oc[dt][2] *= al1; oc[dt][3] *= al1;
        }

        unsigned ph[4][4], pl[4][4];
        #pragma unroll
        for (int c = 0; c < 4; c++) {
            split2(sc[2 * c][0],     sc[2 * c][1],     ph[c][0], pl[c][0]);
            split2(sc[2 * c][2],     sc[2 * c][3],     ph[c][1], pl[c][1]);
            split2(sc[2 * c + 1][0], sc[2 * c + 1][1], ph[c][2], pl[c][2]);
            split2(sc[2 * c + 1][2], sc[2 * c + 1][3], ph[c][3], pl[c][3]);
        }

        #pragma unroll
        for (int c = 0; c < 4; c++) {
            unsigned bhb[4][4], blb[4][4];
            #pragma unroll
            for (int p = 0; p < 4; p++)
                ldm_x4(bhb[p], Vh_b + (unsigned)(poff[p] + 16 * c) * 2);
            #pragma unroll
            for (int p = 0; p < 4; p++)
                ldm_x4(blb[p], Vl_b + (unsigned)(poff[p] + 16 * c) * 2);
            #pragma unroll
            for (int dt = 0; dt < 8; dt++) {
                const unsigned* bh = &bhb[dt >> 1][(dt & 1) * 2];
                const unsigned* bl = &blb[dt >> 1][(dt & 1) * 2];
                mma16816(oc[dt], ph[c], bh);
                mma16816(oc[dt], ph[c], bl);
                mma16816(oc[dt], pl[c], bh);
            }
        }
        __syncthreads();
    }

    float inv0 = 1.f / l0, inv1 = 1.f / l1;
    size_t base0 = (size_t)(b * TSEQ + qg0) * DMODEL + hoff;
    size_t base1 = (size_t)(b * TSEQ + qg1) * DMODEL + hoff;
    #pragma unroll
    for (int dt = 0; dt < 8; dt++) {
        int dcol = dt * 8 + 2 * tig;
        unsigned h0, l0p, h1, l1p;
        split2(oc[dt][0] * inv0, oc[dt][1] * inv0, h0, l0p);
        split2(oc[dt][2] * inv1, oc[dt][3] * inv1, h1, l1p);
        *(unsigned*)(ohi + base0 + dcol) = h0;
        *(unsigned*)(olo + base0 + dcol) = l0p;
        *(unsigned*)(ohi + base1 + dcol) = h1;
        *(unsigned*)(olo + base1 + dcol) = l1p;
    }
}

// -------------------------------- launcher ---------------------------------
extern "C" void kernel_launch(void* const* d_in, const int* in_sizes, int n_in,
                              void* d_out, int out_size)
{
    (void)in_sizes; (void)n_in; (void)out_size;
    const int*   idx   = (const int*)  d_in[0];
    const float* img   = (const float*)d_in[1];
    const float* tok   = (const float*)d_in[2];
    const float* pos   = (const float*)d_in[3];
    const float* ln1w  = (const float*)d_in[4];
    const float* ln1b  = (const float*)d_in[5];
    const float* qkvw  = (const float*)d_in[6];
    const float* outw  = (const float*)d_in[7];
    const float* ln2w  = (const float*)d_in[8];
    const float* ln2b  = (const float*)d_in[9];
    const float* fc1w  = (const float*)d_in[10];
    const float* fc1b  = (const float*)d_in[11];
    const float* fc2w  = (const float*)d_in[12];
    const float* fc2b  = (const float*)d_in[13];
    const float* lnfw  = (const float*)d_in[14];
    const float* lnfb  = (const float*)d_in[15];
    const float* headw = (const float*)d_in[16];
    float* out = (float*)d_out;

    float *x, *qkv;
    __nv_bfloat16 *hhi, *hlo, *athi, *atlo, *ffhi, *fflo, *hchi, *hclo, *whi, *wlo;
    cudaGetSymbolAddress((void**)&x,    g_x);
    cudaGetSymbolAddress((void**)&qkv,  g_qkv);
    cudaGetSymbolAddress((void**)&hhi,  g_h_hi);
    cudaGetSymbolAddress((void**)&hlo,  g_h_lo);
    cudaGetSymbolAddress((void**)&athi, g_at_hi);
    cudaGetSymbolAddress((void**)&atlo, g_at_lo);
    cudaGetSymbolAddress((void**)&ffhi, g_ff_hi);
    cudaGetSymbolAddress((void**)&fflo, g_ff_lo);
    cudaGetSymbolAddress((void**)&hchi, g_hc_hi);
    cudaGetSymbolAddress((void**)&hclo, g_hc_lo);
    cudaGetSymbolAddress((void**)&whi,  g_whi);
    cudaGetSymbolAddress((void**)&wlo,  g_wlo);

    static int attr_done = 0;
    if (!attr_done) {
        cudaFuncSetAttribute(gemm_tc<false, false, false, false>,
                             cudaFuncAttributeMaxDynamicSharedMemorySize, GEMM_SMEM);
        cudaFuncSetAttribute(gemm_tc<false, false, true, false>,
                             cudaFuncAttributeMaxDynamicSharedMemorySize, GEMM_SMEM);
        cudaFuncSetAttribute(gemm_tc<true, true, false, true>,
                             cudaFuncAttributeMaxDynamicSharedMemorySize, GEMM_SMEM);
        cudaFuncSetAttribute(gemm_tc<true, false, true, false>,
                             cudaFuncAttributeMaxDynamicSharedMemorySize, GEMM_SMEM);
        attr_done = 1;
    }

    split_w<<<(NW_QKV / 4 + 255) / 256, 256>>>(qkvw,  whi,            wlo,            NW_QKV / 4);
    split_w<<<(NW_OUT / 4 + 255) / 256, 256>>>(outw,  whi + OFF_OUT,  wlo + OFF_OUT,  NW_OUT / 4);
    split_w<<<(NW_FC1 / 4 + 255) / 256, 256>>>(fc1w,  whi + OFF_FC1,  wlo + OFF_FC1,  NW_FC1 / 4);
    split_w<<<(NW_FC2 / 4 + 255) / 256, 256>>>(fc2w,  whi + OFF_FC2,  wlo + OFF_FC2,  NW_FC2 / 4);
    split_w<<<(NW_HEAD / 4 + 255) / 256, 256>>>(headw, whi + OFF_HEAD, wlo + OFF_HEAD, NW_HEAD / 4);

    embed_kernel<<<4096, 256>>>(idx, img, tok, pos, x);

    for (int l = 0; l < NLAYER; l++) {
        size_t oq = (size_t)l * 3 * DMODEL * DMODEL;
        size_t oo = OFF_OUT + (size_t)l * DMODEL * DMODEL;
        size_t o1 = OFF_FC1 + (size_t)l * DFFDIM * DMODEL;
        size_t o2 = OFF_FC2 + (size_t)l * DMODEL * DFFDIM;

        ln_kernel<<<BROWS, 256>>>(x, ln1w + l * DMODEL, ln1b + l * DMODEL, hhi, hlo, 0);
        gemm_tc<false, false, false, false><<<dim3(3 * DMODEL / 256, BROWS / 128), 256, GEMM_SMEM>>>(
            hhi, hlo, whi + oq, wlo + oq, nullptr, nullptr, qkv, nullptr, nullptr,
            BROWS, 3 * DMODEL, DMODEL);
        attn_tc<<<dim3(TSEQ / 64, NHEAD, 2), 128>>>(qkv, athi, atlo);
        gemm_tc<false, false, true, false><<<dim3(DMODEL / 256, BROWS / 128), 256, GEMM_SMEM>>>(
            athi, atlo, whi + oo, wlo + oo, nullptr, x, x, nullptr, nullptr,
            BROWS, DMODEL, DMODEL);
        ln_kernel<<<BROWS, 256>>>(x, ln2w + l * DMODEL, ln2b + l * DMODEL, hhi, hlo, 0);
        gemm_tc<true, true, false, true><<<dim3(DFFDIM / 256, BROWS / 128), 256, GEMM_SMEM>>>(
            hhi, hlo, whi + o1, wlo + o1, fc1b + l * DFFDIM, nullptr, nullptr, ffhi, fflo,
            BROWS, DFFDIM, DMODEL);
        gemm_tc<true, false, true, false><<<dim3(DMODEL / 256, BROWS / 128), 256, GEMM_SMEM>>>(
            ffhi, fflo, whi + o2, wlo + o2, fc2b + l * DMODEL, x, x, nullptr, nullptr,
            BROWS, DMODEL, DFFDIM);
    }

    ln_kernel<<<MTEXT, 256>>>(x, lnfw, lnfb, hchi, hclo, 1);
    gemm_tc<false, false, false, false><<<dim3(VOCABN / 256, MTEXT / 128), 256, GEMM_SMEM>>>(
        hchi, hclo, whi + OFF_HEAD, wlo + OFF_HEAD, nullptr, nullptr, out, nullptr, nullptr,
        MTEXT, VOCABN, DMODEL);
}

// round 17
// speedup vs baseline: 1.2446x; 1.0207x over previous
#include <cuda_runtime.h>
#include <cuda_bf16.h>
#include <cstdint>

// ---------------------------------------------------------------------------
// TinyGPT forward. GEMMs: mma.sync bf16x3, 128x128 CTA tile, 64x32 warp tile,
// cp.async 2-stage, __launch_bounds__(256,2) for 2 CTAs/SM (latency hiding).
// Attention: mma.sync bf16x3 flash. LN/embed SIMT.
// B=2, T=2048 (NV=256 vision + 1792 text), D=1024, H=16, DH=64, L=8,
// DFF=4096, VOCAB=32000. Output: fp32 logits [2, 1792, 32000].
// ---------------------------------------------------------------------------

#define TSEQ   2048
#define NVTOK  256
#define TTEXT  1792
#define DMODEL 1024
#define DFFDIM 4096
#define NHEAD  16
#define DHEAD  64
#define NLAYER 8
#define VOCABN 32000
#define BROWS  (2 * TSEQ)
#define MTEXT  (2 * TTEXT)

#define NW_QKV  (NLAYER * 3 * DMODEL * DMODEL)
#define NW_OUT  (NLAYER * DMODEL * DMODEL)
#define NW_FC1  (NLAYER * DFFDIM * DMODEL)
#define NW_FC2  (NLAYER * DMODEL * DFFDIM)
#define NW_HEAD (VOCABN * DMODEL)
#define OFF_OUT  NW_QKV
#define OFF_FC1  (OFF_OUT + NW_OUT)
#define OFF_FC2  (OFF_FC1 + NW_FC1)
#define OFF_HEAD (OFF_FC2 + NW_FC2)
#define NW_TOT   (OFF_HEAD + NW_HEAD)

// ------------------------- scratch (device globals) ------------------------
__device__ float g_x  [BROWS * DMODEL];
__device__ float g_qkv[BROWS * 3 * DMODEL];
__device__ __nv_bfloat16 g_h_hi [BROWS * DMODEL],  g_h_lo [BROWS * DMODEL];
__device__ __nv_bfloat16 g_at_hi[BROWS * DMODEL],  g_at_lo[BROWS * DMODEL];
__device__ __nv_bfloat16 g_ff_hi[BROWS * DFFDIM],  g_ff_lo[BROWS * DFFDIM];
__device__ __nv_bfloat16 g_hc_hi[MTEXT * DMODEL],  g_hc_lo[MTEXT * DMODEL];
__device__ __nv_bfloat16 g_whi[NW_TOT], g_wlo[NW_TOT];

// ------------------------------ helpers ------------------------------------
__device__ __forceinline__ void mma16816(float c[4], const unsigned a[4],
                                         const unsigned b[2])
{
    asm volatile(
        "mma.sync.aligned.m16n8k16.row.col.f32.bf16.bf16.f32 "
        "{%0,%1,%2,%3}, {%4,%5,%6,%7}, {%8,%9}, {%0,%1,%2,%3};"
        : "+f"(c[0]), "+f"(c[1]), "+f"(c[2]), "+f"(c[3])
        : "r"(a[0]), "r"(a[1]), "r"(a[2]), "r"(a[3]), "r"(b[0]), "r"(b[1]));
}
__device__ __forceinline__ void ldm_x4(unsigned r[4], unsigned addr)
{
    asm volatile(
        "ldmatrix.sync.aligned.m8n8.x4.shared.b16 {%0,%1,%2,%3}, [%4];"
        : "=r"(r[0]), "=r"(r[1]), "=r"(r[2]), "=r"(r[3]) : "r"(addr));
}
__device__ __forceinline__ void split2(float x, float y, unsigned& hi, unsigned& lo)
{
    __nv_bfloat16 hx = __float2bfloat16(x);
    __nv_bfloat16 hy = __float2bfloat16(y);
    __nv_bfloat162 H(hx, hy);
    hi = *(unsigned*)&H;
    __nv_bfloat162 L = __floats2bfloat162_rn(x - __bfloat162float(hx),
                                             y - __bfloat162float(hy));
    lo = *(unsigned*)&L;
}
__device__ __forceinline__ void split_store4(__nv_bfloat16* hi, __nv_bfloat16* lo,
                                             float4 v)
{
    __nv_bfloat16 h0 = __float2bfloat16(v.x);
    __nv_bfloat16 h1 = __float2bfloat16(v.y);
    __nv_bfloat16 h2 = __float2bfloat16(v.z);
    __nv_bfloat16 h3 = __float2bfloat16(v.w);
    __nv_bfloat16 l0 = __float2bfloat16(v.x - __bfloat162float(h0));
    __nv_bfloat16 l1 = __float2bfloat16(v.y - __bfloat162float(h1));
    __nv_bfloat16 l2 = __float2bfloat16(v.z - __bfloat162float(h2));
    __nv_bfloat16 l3 = __float2bfloat16(v.w - __bfloat162float(h3));
    *(__nv_bfloat162*)(hi)     = __nv_bfloat162(h0, h1);
    *(__nv_bfloat162*)(hi + 2) = __nv_bfloat162(h2, h3);
    *(__nv_bfloat162*)(lo)     = __nv_bfloat162(l0, l1);
    *(__nv_bfloat162*)(lo + 2) = __nv_bfloat162(l2, l3);
}

#define CP_ASYNC16(saddr, gptr) \
    asm volatile("cp.async.ca.shared.global [%0], [%1], 16;" \
                 :: "r"(saddr), "l"(gptr) : "memory")
#define CP_COMMIT() asm volatile("cp.async.commit_group;" ::: "memory")
#define CP_WAIT(n)  asm volatile("cp.async.wait_group %0;" :: "n"(n) : "memory")

// ----------------------- weight pre-split (per launch) ---------------------
__global__ __launch_bounds__(256)
void split_w(const float* __restrict__ src, __nv_bfloat16* __restrict__ hi,
             __nv_bfloat16* __restrict__ lo, int n4)
{
    int i = blockIdx.x * 256 + threadIdx.x;
    if (i >= n4) return;
    float4 v = ((const float4*)src)[i];
    split_store4(hi + 4 * (size_t)i, lo + 4 * (size_t)i, v);
}

// ------------------------------- embedding ---------------------------------
__global__ __launch_bounds__(256)
void embed_kernel(const int* __restrict__ idx, const float* __restrict__ img,
                  const float* __restrict__ tok, const float* __restrict__ pos,
                  float* __restrict__ x)
{
    int i = blockIdx.x * 256 + threadIdx.x;
    int d4 = (i & 255) << 2;
    int t  = (i >> 8) & (TSEQ - 1);
    int b  = i >> 19;

    float4 base;
    if (t < NVTOK) {
        base = *(const float4*)(img + ((size_t)(b * NVTOK + t) * DMODEL) + d4);
    } else {
        int tid = idx[b * TTEXT + (t - NVTOK)];
        base = *(const float4*)(tok + (size_t)tid * DMODEL + d4);
    }
    float4 p = *(const float4*)(pos + (size_t)t * DMODEL + d4);
    base.x += p.x; base.y += p.y; base.z += p.z; base.w += p.w;
    *(float4*)(x + (size_t)(b * TSEQ + t) * DMODEL + d4) = base;
}

// ------------------------------- layernorm ---------------------------------
__global__ __launch_bounds__(256)
void ln_kernel(const float* __restrict__ x, const float* __restrict__ w,
               const float* __restrict__ bias,
               __nv_bfloat16* __restrict__ ohi, __nv_bfloat16* __restrict__ olo,
               int remap)
{
    __shared__ float sh1[8];
    __shared__ float sh2[8];
    int r = blockIdx.x;
    int rin = remap ? ((r / TTEXT) * TSEQ + NVTOK + (r % TTEXT)) : r;
    int tid = threadIdx.x;

    float4 v = *(const float4*)(x + (size_t)rin * DMODEL + (tid << 2));
    float s = v.x + v.y + v.z + v.w;
    #pragma unroll
    for (int o = 16; o > 0; o >>= 1) s += __shfl_xor_sync(0xffffffffu, s, o);
    if ((tid & 31) == 0) sh1[tid >> 5] = s;
    __syncthreads();
    float tot = sh1[0] + sh1[1] + sh1[2] + sh1[3] + sh1[4] + sh1[5] + sh1[6] + sh1[7];
    float mu = tot * (1.0f / DMODEL);

    float d0 = v.x - mu, d1 = v.y - mu, d2 = v.z - mu, d3 = v.w - mu;
    float ss = d0 * d0 + d1 * d1 + d2 * d2 + d3 * d3;
    #pragma unroll
    for (int o = 16; o > 0; o >>= 1) ss += __shfl_xor_sync(0xffffffffu, ss, o);
    if ((tid & 31) == 0) sh2[tid >> 5] = ss;
    __syncthreads();
    float tot2 = sh2[0] + sh2[1] + sh2[2] + sh2[3] + sh2[4] + sh2[5] + sh2[6] + sh2[7];
    float rs = rsqrtf(tot2 * (1.0f / DMODEL) + 1e-5f);

    float4 wv = *(const float4*)(w + (tid << 2));
    float4 bv = *(const float4*)(bias + (tid << 2));
    float4 o4;
    o4.x = d0 * rs * wv.x + bv.x;
    o4.y = d1 * rs * wv.y + bv.y;
    o4.z = d2 * rs * wv.z + bv.z;
    o4.w = d3 * rs * wv.w + bv.w;
    size_t off = (size_t)r * DMODEL + (tid << 2);
    split_store4(ohi + off, olo + off, o4);
}

// ----------------------- tensor-core GEMM (bf16x3) -------------------------
// Pre-split bf16 hi/lo operands. CTA tile 128x128, BK=32, 256 thr, 8 warps,
// warp tile 64x32. cp.async 2-stage. 2 CTAs/SM via launch_bounds.
// Requires M%128, N%128, K%32.
#define KP 40
// stage layout (bytes): Ah[0,10240) Al[10240,20480) Bh[20480,30720) Bl[30720,40960)
#define STAGEB 40960
#define GEMM_SMEM (2 * STAGEB)

template<bool BIAS, bool RELU, bool RES, bool SPLITOUT>
__global__ __launch_bounds__(256, 2)
void gemm_tc(const __nv_bfloat16* __restrict__ Ahi, const __nv_bfloat16* __restrict__ Alo,
             const __nv_bfloat16* __restrict__ Whi, const __nv_bfloat16* __restrict__ Wlo,
             const float* __restrict__ bias, const float* __restrict__ Res,
             float* __restrict__ C, __nv_bfloat16* __restrict__ Chi,
             __nv_bfloat16* __restrict__ Clo, int M, int N, int K)
{
    extern __shared__ __nv_bfloat16 sm[];

    int n0 = blockIdx.x << 7;
    int m0 = blockIdx.y << 7;
    int tid = threadIdx.x;
    int wid = tid >> 5, lane = tid & 31;
    int grp = lane >> 2, tig = lane & 3;
    int lt = lane & 7, seg = lane >> 3;
    int wm = (wid >> 2) << 6;     // 0 or 64
    int wn = (wid & 3) << 5;      // 0,32,64,96

    // loader: row r0 = tid>>1 (0..127), elem chunk kc = (tid&1)*16
    int r0 = tid >> 1;
    int kc = (tid & 1) << 4;
    const __nv_bfloat16* Ah_g = Ahi + (size_t)(m0 + r0) * K + kc;
    const __nv_bfloat16* Al_g = Alo + (size_t)(m0 + r0) * K + kc;
    const __nv_bfloat16* Bh_g = Whi + (size_t)(n0 + r0) * K + kc;
    const __nv_bfloat16* Bl_g = Wlo + (size_t)(n0 + r0) * K + kc;
    unsigned smbase = (unsigned)__cvta_generic_to_shared(sm);
    unsigned soff = (unsigned)(r0 * KP + kc) * 2;

    // ldmatrix per-lane element offsets
    int aoff[4], boff[2];
    #pragma unroll
    for (int mi = 0; mi < 4; mi++)
        aoff[mi] = (wm + mi * 16 + (seg & 1) * 8 + lt) * KP + (seg >> 1) * 8;
    #pragma unroll
    for (int p = 0; p < 2; p++)
        boff[p] = (wn + (2 * p + (seg >> 1)) * 8 + lt) * KP + (seg & 1) * 8;

    float acc[4][4][4];
    #pragma unroll
    for (int mi = 0; mi < 4; mi++)
        #pragma unroll
        for (int ni = 0; ni < 4; ni++)
            #pragma unroll
            for (int q = 0; q < 4; q++) acc[mi][ni][q] = 0.f;

    // stage issue: 8 cp.async per thread
    auto issue = [&](int buf, int kt) {
        unsigned so = smbase + buf * STAGEB + soff;
        CP_ASYNC16(so,              Ah_g + kt);
        CP_ASYNC16(so + 16,         Ah_g + kt + 8);
        CP_ASYNC16(so + 10240,      Al_g + kt);
        CP_ASYNC16(so + 10240 + 16, Al_g + kt + 8);
        CP_ASYNC16(so + 20480,      Bh_g + kt);
        CP_ASYNC16(so + 20480 + 16, Bh_g + kt + 8);
        CP_ASYNC16(so + 30720,      Bl_g + kt);
        CP_ASYNC16(so + 30720 + 16, Bl_g + kt + 8);
        CP_COMMIT();
    };

    issue(0, 0);

    int nt = K >> 5;
    for (int t = 0; t < nt; t++) {
        int cur = t & 1;
        if (t + 1 < nt) {
            issue(cur ^ 1, (t + 1) << 5);
            CP_WAIT(1);
        } else {
            CP_WAIT(0);
        }
        __syncthreads();

        unsigned Ah_b = smbase + cur * STAGEB;
        unsigned Al_b = Ah_b + 10240;
        unsigned Bh_b = Ah_b + 20480;
        unsigned Bl_b = Ah_b + 30720;

        #pragma unroll
        for (int ks = 0; ks < 32; ks += 16) {
            unsigned ah[4][4], al[4][4], bhb[2][4], blb[2][4];
            #pragma unroll
            for (int mi = 0; mi < 4; mi++)
                ldm_x4(ah[mi], Ah_b + (unsigned)(aoff[mi] + ks) * 2);
            #pragma unroll
            for (int mi = 0; mi < 4; mi++)
                ldm_x4(al[mi], Al_b + (unsigned)(aoff[mi] + ks) * 2);
            #pragma unroll
            for (int p = 0; p < 2; p++)
                ldm_x4(bhb[p], Bh_b + (unsigned)(boff[p] + ks) * 2);
            #pragma unroll
            for (int p = 0; p < 2; p++)
                ldm_x4(blb[p], Bl_b + (unsigned)(boff[p] + ks) * 2);

            #pragma unroll
            for (int mi = 0; mi < 4; mi++)
                #pragma unroll
                for (int ni = 0; ni < 4; ni++) {
                    const unsigned* bh = &bhb[ni >> 1][(ni & 1) * 2];
                    const unsigned* bl = &blb[ni >> 1][(ni & 1) * 2];
                    mma16816(acc[mi][ni], ah[mi], bh);
                    mma16816(acc[mi][ni], ah[mi], bl);
                    mma16816(acc[mi][ni], al[mi], bh);
                }
        }
        __syncthreads();
    }

    #pragma unroll
    for (int mi = 0; mi < 4; mi++) {
        #pragma unroll
        for (int ni = 0; ni < 4; ni++) {
            int row = m0 + wm + mi * 16 + grp;
            int col = n0 + wn + ni * 8 + 2 * tig;
            float2 v0 = make_float2(acc[mi][ni][0], acc[mi][ni][1]);
            float2 v1 = make_float2(acc[mi][ni][2], acc[mi][ni][3]);
            if (BIAS) {
                float2 bv = *(const float2*)(bias + col);
                v0.x += bv.x; v0.y += bv.y; v1.x += bv.x; v1.y += bv.y;
            }
            if (RELU) {
                v0.x = fmaxf(v0.x, 0.f); v0.y = fmaxf(v0.y, 0.f);
                v1.x = fmaxf(v1.x, 0.f); v1.y = fmaxf(v1.y, 0.f);
            }
            if (RES) {
                float2 r0v = *(const float2*)(Res + (size_t)row * N + col);
                float2 r1v = *(const float2*)(Res + (size_t)(row + 8) * N + col);
                v0.x += r0v.x; v0.y += r0v.y; v1.x += r1v.x; v1.y += r1v.y;
            }
            if (SPLITOUT) {
                unsigned h0, l0, h1, l1;
                split2(v0.x, v0.y, h0, l0);
                split2(v1.x, v1.y, h1, l1);
                *(unsigned*)(Chi + (size_t)row * N + col) = h0;
                *(unsigned*)(Clo + (size_t)row * N + col) = l0;
                *(unsigned*)(Chi + (size_t)(row + 8) * N + col) = h1;
                *(unsigned*)(Clo + (size_t)(row + 8) * N + col) = l1;
            } else {
                *(float2*)(C + (size_t)row * N + col) = v0;
                *(float2*)(C + (size_t)(row + 8) * N + col) = v1;
            }
        }
    }
}

// ------------------- tensor-core flash attention (bf16x3) ------------------
#define AKP 72

__global__ __launch_bounds__(128, 3)
void attn_tc(const float* __restrict__ qkv,
             __nv_bfloat16* __restrict__ ohi, __nv_bfloat16* __restrict__ olo)
{
    const int QKVD = 3 * DMODEL;
    int qt0 = blockIdx.x << 6;
    int h = blockIdx.y, b = blockIdx.z;
    int tid = threadIdx.x;
    int warp = tid >> 5, lane = tid & 31;
    int grp = lane >> 2, tig = lane & 3;
    int lt = lane & 7, seg = lane >> 3;
    int wm = warp << 4;
    int hoff = h * DHEAD;

    __shared__ __nv_bfloat16 Ksh[64][AKP], Ksl[64][AKP];
    __shared__ __nv_bfloat16 Vth[64][AKP], Vtl[64][AKP];

    unsigned Kh_b = (unsigned)__cvta_generic_to_shared(&Ksh[0][0]);
    unsigned Kl_b = (unsigned)__cvta_generic_to_shared(&Ksl[0][0]);
    unsigned Vh_b = (unsigned)__cvta_generic_to_shared(&Vth[0][0]);
    unsigned Vl_b = (unsigned)__cvta_generic_to_shared(&Vtl[0][0]);

    int poff[4];
    #pragma unroll
    for (int p = 0; p < 4; p++)
        poff[p] = ((2 * p + (seg >> 1)) * 8 + lt) * AKP + (seg & 1) * 8;

    unsigned qh[4][4], ql[4][4];
    {
        const float* Q0 = qkv + (size_t)(b * TSEQ + qt0 + wm + grp) * QKVD + hoff;
        const float* Q1 = Q0 + (size_t)8 * QKVD;
        #pragma unroll
        for (int c = 0; c < 4; c++) {
            int k0 = 16 * c + 2 * tig;
            float2 f0 = *(const float2*)(Q0 + k0);
            float2 f1 = *(const float2*)(Q1 + k0);
            float2 f2 = *(const float2*)(Q0 + k0 + 8);
            float2 f3 = *(const float2*)(Q1 + k0 + 8);
            split2(f0.x * 0.125f, f0.y * 0.125f, qh[c][0], ql[c][0]);
            split2(f1.x * 0.125f, f1.y * 0.125f, qh[c][1], ql[c][1]);
            split2(f2.x * 0.125f, f2.y * 0.125f, qh[c][2], ql[c][2]);
            split2(f3.x * 0.125f, f3.y * 0.125f, qh[c][3], ql[c][3]);
        }
    }

    float oc[8][4];
    #pragma unroll
    for (int dt = 0; dt < 8; dt++)
        #pragma unroll
        for (int q = 0; q < 4; q++) oc[dt][q] = 0.f;
    float m0 = -1e30f, m1 = -1e30f, l0 = 0.f, l1 = 0.f;

    int qg0 = qt0 + wm + grp, qg1 = qg0 + 8;
    int ktend = (qt0 >= NVTOK) ? (qt0 + 64) : TSEQ;

    for (int kt0 = 0; kt0 < ktend; kt0 += 64) {
        #pragma unroll
        for (int i = 0; i < 8; i++) {
            int idx = tid + (i << 7);
            int key = idx >> 4, d4 = (idx & 15) << 2;
            const float* bp = qkv + (size_t)(b * TSEQ + kt0 + key) * QKVD + hoff + d4;
            float4 kv = *(const float4*)(bp + DMODEL);
            split_store4(&Ksh[key][d4], &Ksl[key][d4], kv);
            float4 vv = *(const float4*)(bp + 2 * DMODEL);
            float vf[4] = {vv.x, vv.y, vv.z, vv.w};
            #pragma unroll
            for (int j = 0; j < 4; j++) {
                __nv_bfloat16 hi = __float2bfloat16(vf[j]);
                Vth[d4 + j][key] = hi;
                Vtl[d4 + j][key] = __float2bfloat16(vf[j] - __bfloat162float(hi));
            }
        }
        __syncthreads();

        float sc[8][4];
        #pragma unroll
        for (int nt = 0; nt < 8; nt++)
            #pragma unroll
            for (int q = 0; q < 4; q++) sc[nt][q] = 0.f;

        #pragma unroll
        for (int c = 0; c < 4; c++) {
            unsigned bhb[4][4], blb[4][4];
            #pragma unroll
            for (int p = 0; p < 4; p++)
                ldm_x4(bhb[p], Kh_b + (unsigned)(poff[p] + 16 * c) * 2);
            #pragma unroll
            for (int p = 0; p < 4; p++)
                ldm_x4(blb[p], Kl_b + (unsigned)(poff[p] + 16 * c) * 2);
            #pragma unroll
            for (int nt = 0; nt < 8; nt++) {
                const unsigned* bh = &bhb[nt >> 1][(nt & 1) * 2];
                const unsigned* bl = &blb[nt >> 1][(nt & 1) * 2];
                mma16816(sc[nt], qh[c], bh);
                mma16816(sc[nt], qh[c], bl);
                mma16816(sc[nt], ql[c], bh);
            }
        }

        #pragma unroll
        for (int nt = 0; nt < 8; nt++) {
            int kg0 = kt0 + nt * 8 + 2 * tig;
            int kg1 = kg0 + 1;
            if (!((qg0 < NVTOK) || (kg0 <= qg0))) sc[nt][0] = -1e30f;
            if (!((qg0 < NVTOK) || (kg1 <= qg0))) sc[nt][1] = -1e30f;
            if (!((qg1 < NVTOK) || (kg0 <= qg1))) sc[nt][2] = -1e30f;
            if (!((qg1 < NVTOK) || (kg1 <= qg1))) sc[nt][3] = -1e30f;
        }

        float mx0 = -1e30f, mx1 = -1e30f;
        #pragma unroll
        for (int nt = 0; nt < 8; nt++) {
            mx0 = fmaxf(mx0, fmaxf(sc[nt][0], sc[nt][1]));
            mx1 = fmaxf(mx1, fmaxf(sc[nt][2], sc[nt][3]));
        }
        mx0 = fmaxf(mx0, __shfl_xor_sync(0xffffffffu, mx0, 1));
        mx0 = fmaxf(mx0, __shfl_xor_sync(0xffffffffu, mx0, 2));
        mx1 = fmaxf(mx1, __shfl_xor_sync(0xffffffffu, mx1, 1));
        mx1 = fmaxf(mx1, __shfl_xor_sync(0xffffffffu, mx1, 2));
        float mn0 = fmaxf(m0, mx0), mn1 = fmaxf(m1, mx1);
        float al0 = __expf(m0 - mn0), al1 = __expf(m1 - mn1);
        m0 = mn0; m1 = mn1;

        float sum0 = 0.f, sum1 = 0.f;
        #pragma unroll
        for (int nt = 0; nt < 8; nt++) {
            sc[nt][0] = __expf(sc[nt][0] - mn0); sum0 += sc[nt][0];
            sc[nt][1] = __expf(sc[nt][1] - mn0); sum0 += sc[nt][1];
            sc[nt][2] = __expf(sc[nt][2] - mn1); sum1 += sc[nt][2];
            sc[nt][3] = __expf(sc[nt][3] - mn1); sum1 += sc[nt][3];
        }
        sum0 += __shfl_xor_sync(0xffffffffu, sum0, 1);
        sum0 += __shfl_xor_sync(0xffffffffu, sum0, 2);
        sum1 += __shfl_xor_sync(0xffffffffu, sum1, 1);
        sum1 += __shfl_xor_sync(0xffffffffu, sum1, 2);
        l0 = l0 * al0 + sum0;
        l1 = l1 * al1 + sum1;

        #pragma unroll
        for (int dt = 0; dt < 8; dt++) {
            oc[dt][0] *= al0; oc[dt][1] *= al0;
            oc[dt][2] *= al1; oc[dt][3] *= al1;
        }

        unsigned ph[4][4], pl[4][4];
        #pragma unroll
        for (int c = 0; c < 4; c++) {
            split2(sc[2 * c][0],     sc[2 * c][1],     ph[c][0], pl[c][0]);
            split2(sc[2 * c][2],     sc[2 * c][3],     ph[c][1], pl[c][1]);
            split2(sc[2 * c + 1][0], sc[2 * c + 1][1], ph[c][2], pl[c][2]);
            split2(sc[2 * c + 1][2], sc[2 * c + 1][3], ph[c][3], pl[c][3]);
        }

        #pragma unroll
        for (int c = 0; c < 4; c++) {
            unsigned bhb[4][4], blb[4][4];
            #pragma unroll
            for (int p = 0; p < 4; p++)
                ldm_x4(bhb[p], Vh_b + (unsigned)(poff[p] + 16 * c) * 2);
            #pragma unroll
            for (int p = 0; p < 4; p++)
                ldm_x4(blb[p], Vl_b + (unsigned)(poff[p] + 16 * c) * 2);
            #pragma unroll
            for (int dt = 0; dt < 8; dt++) {
                const unsigned* bh = &bhb[dt >> 1][(dt & 1) * 2];
                const unsigned* bl = &blb[dt >> 1][(dt & 1) * 2];
                mma16816(oc[dt], ph[c], bh);
                mma16816(oc[dt], ph[c], bl);
                mma16816(oc[dt], pl[c], bh);
            }
        }
        __syncthreads();
    }

    float inv0 = 1.f / l0, inv1 = 1.f / l1;
    size_t base0 = (size_t)(b * TSEQ + qg0) * DMODEL + hoff;
    size_t base1 = (size_t)(b * TSEQ + qg1) * DMODEL + hoff;
    #pragma unroll
    for (int dt = 0; dt < 8; dt++) {
        int dcol = dt * 8 + 2 * tig;
        unsigned h0, l0p, h1, l1p;
        split2(oc[dt][0] * inv0, oc[dt][1] * inv0, h0, l0p);
        split2(oc[dt][2] * inv1, oc[dt][3] * inv1, h1, l1p);
        *(unsigned*)(ohi + base0 + dcol) = h0;
        *(unsigned*)(olo + base0 + dcol) = l0p;
        *(unsigned*)(ohi + base1 + dcol) = h1;
        *(unsigned*)(olo + base1 + dcol) = l1p;
    }
}

// -------------------------------- launcher ---------------------------------
extern "C" void kernel_launch(void* const* d_in, const int* in_sizes, int n_in,
                              void* d_out, int out_size)
{
    (void)in_sizes; (void)n_in; (void)out_size;
    const int*   idx   = (const int*)  d_in[0];
    const float* img   = (const float*)d_in[1];
    const float* tok   = (const float*)d_in[2];
    const float* pos   = (const float*)d_in[3];
    const float* ln1w  = (const float*)d_in[4];
    const float* ln1b  = (const float*)d_in[5];
    const float* qkvw  = (const float*)d_in[6];
    const float* outw  = (const float*)d_in[7];
    const float* ln2w  = (const float*)d_in[8];
    const float* ln2b  = (const float*)d_in[9];
    const float* fc1w  = (const float*)d_in[10];
    const float* fc1b  = (const float*)d_in[11];
    const float* fc2w  = (const float*)d_in[12];
    const float* fc2b  = (const float*)d_in[13];
    const float* lnfw  = (const float*)d_in[14];
    const float* lnfb  = (const float*)d_in[15];
    const float* headw = (const float*)d_in[16];
    float* out = (float*)d_out;

    float *x, *qkv;
    __nv_bfloat16 *hhi, *hlo, *athi, *atlo, *ffhi, *fflo, *hchi, *hclo, *whi, *wlo;
    cudaGetSymbolAddress((void**)&x,    g_x);
    cudaGetSymbolAddress((void**)&qkv,  g_qkv);
    cudaGetSymbolAddress((void**)&hhi,  g_h_hi);
    cudaGetSymbolAddress((void**)&hlo,  g_h_lo);
    cudaGetSymbolAddress((void**)&athi, g_at_hi);
    cudaGetSymbolAddress((void**)&atlo, g_at_lo);
    cudaGetSymbolAddress((void**)&ffhi, g_ff_hi);
    cudaGetSymbolAddress((void**)&fflo, g_ff_lo);
    cudaGetSymbolAddress((void**)&hchi, g_hc_hi);
    cudaGetSymbolAddress((void**)&hclo, g_hc_lo);
    cudaGetSymbolAddress((void**)&whi,  g_whi);
    cudaGetSymbolAddress((void**)&wlo,  g_wlo);

    static int attr_done = 0;
    if (!attr_done) {
        cudaFuncSetAttribute(gemm_tc<false, false, false, false>,
                             cudaFuncAttributeMaxDynamicSharedMemorySize, GEMM_SMEM);
        cudaFuncSetAttribute(gemm_tc<false, false, true, false>,
                             cudaFuncAttributeMaxDynamicSharedMemorySize, GEMM_SMEM);
        cudaFuncSetAttribute(gemm_tc<true, true, false, true>,
                             cudaFuncAttributeMaxDynamicSharedMemorySize, GEMM_SMEM);
        cudaFuncSetAttribute(gemm_tc<true, false, true, false>,
                             cudaFuncAttributeMaxDynamicSharedMemorySize, GEMM_SMEM);
        attr_done = 1;
    }

    split_w<<<(NW_QKV / 4 + 255) / 256, 256>>>(qkvw,  whi,            wlo,            NW_QKV / 4);
    split_w<<<(NW_OUT / 4 + 255) / 256, 256>>>(outw,  whi + OFF_OUT,  wlo + OFF_OUT,  NW_OUT / 4);
    split_w<<<(NW_FC1 / 4 + 255) / 256, 256>>>(fc1w,  whi + OFF_FC1,  wlo + OFF_FC1,  NW_FC1 / 4);
    split_w<<<(NW_FC2 / 4 + 255) / 256, 256>>>(fc2w,  whi + OFF_FC2,  wlo + OFF_FC2,  NW_FC2 / 4);
    split_w<<<(NW_HEAD / 4 + 255) / 256, 256>>>(headw, whi + OFF_HEAD, wlo + OFF_HEAD, NW_HEAD / 4);

    embed_kernel<<<4096, 256>>>(idx, img, tok, pos, x);

    for (int l = 0; l < NLAYER; l++) {
        size_t oq = (size_t)l * 3 * DMODEL * DMODEL;
        size_t oo = OFF_OUT + (size_t)l * DMODEL * DMODEL;
        size_t o1 = OFF_FC1 + (size_t)l * DFFDIM * DMODEL;
        size_t o2 = OFF_FC2 + (size_t)l * DMODEL * DFFDIM;

        ln_kernel<<<BROWS, 256>>>(x, ln1w + l * DMODEL, ln1b + l * DMODEL, hhi, hlo, 0);
        gemm_tc<false, false, false, false><<<dim3(3 * DMODEL / 128, BROWS / 128), 256, GEMM_SMEM>>>(
            hhi, hlo, whi + oq, wlo + oq, nullptr, nullptr, qkv, nullptr, nullptr,
            BROWS, 3 * DMODEL, DMODEL);
        attn_tc<<<dim3(TSEQ / 64, NHEAD, 2), 128>>>(qkv, athi, atlo);
        gemm_tc<false, false, true, false><<<dim3(DMODEL / 128, BROWS / 128), 256, GEMM_SMEM>>>(
            athi, atlo, whi + oo, wlo + oo, nullptr, x, x, nullptr, nullptr,
            BROWS, DMODEL, DMODEL);
        ln_kernel<<<BROWS, 256>>>(x, ln2w + l * DMODEL, ln2b + l * DMODEL, hhi, hlo, 0);
        gemm_tc<true, true, false, true><<<dim3(DFFDIM / 128, BROWS / 128), 256, GEMM_SMEM>>>(
            hhi, hlo, whi + o1, wlo + o1, fc1b + l * DFFDIM, nullptr, nullptr, ffhi, fflo,
            BROWS, DFFDIM, DMODEL);
        gemm_tc<true, false, true, false><<<dim3(DMODEL / 128, BROWS / 128), 256, GEMM_SMEM>>>(
            ffhi, fflo, whi + o2, wlo + o2, fc2b + l * DMODEL, x, x, nullptr, nullptr,
            BROWS, DMODEL, DFFDIM);
    }

    ln_kernel<<<MTEXT, 256>>>(x, lnfw, lnfb, hchi, hclo, 1);
    gemm_tc<false, false, false, false><<<dim3(VOCABN / 128, MTEXT / 128), 256, GEMM_SMEM>>>(
        hchi, hclo, whi + OFF_HEAD, wlo + OFF_HEAD, nullptr, nullptr, out, nullptr, nullptr,
        MTEXT, VOCABN, DMODEL);
}